// round 15
// baseline (speedup 1.0000x reference)
#include <cuda_runtime.h>
#include <cuda_fp16.h>
#include <math.h>
#include <stdint.h>

#define N_RBF 300
#define NBUCK 512
#define N_MAXN 100352
#define E_MAXE 400384
#define GE2_MAX 6256
#define RBF_STEP (30.0f/299.0f)
#define RBF_INV  (299.0f/30.0f)
#define SLD 40
#define WK 32
#define BUFB 10240
#define DSMEM2 40960
#define DSMEM4 35840
#define DSMEM5 60416

__device__ float  g_h  [(size_t)N_MAXN*128];
__device__ __half g_ee [2*(size_t)E_MAXE*128];
__device__ __half g_tmp[(size_t)N_MAXN*128];
__device__ float  g_P  [3*400*428];
__device__ int    g_perm[E_MAXE];
__device__ int    g_hist[2*NBUCK];
__device__ int    g_klo [GE2_MAX];
__device__ __half g_rAh[(size_t)E_MAXE*WK];
__device__ __half g_W1h[3*512*384];
__device__ __half g_We2h[3*128*448];
__device__ __half g_Wn1h[3*128*128];
__device__ __half g_Wn2h[3*128*128];
__device__ __half g_Wch [3*128*128];
__device__ __half g_Wr1h[128*128];

__device__ __forceinline__ uint32_t smem_u32(const void* p) {
    uint32_t a;
    asm("{ .reg .u64 t; cvta.to.shared.u64 t, %1; cvt.u32.u64 %0, t; }" : "=r"(a) : "l"(p));
    return a;
}
__device__ __forceinline__ void ldmx4(uint32_t& r0, uint32_t& r1, uint32_t& r2, uint32_t& r3, uint32_t a) {
    asm volatile("ldmatrix.sync.aligned.m8n8.x4.shared.b16 {%0,%1,%2,%3}, [%4];"
        : "=r"(r0), "=r"(r1), "=r"(r2), "=r"(r3) : "r"(a));
}
__device__ __forceinline__ void mma16816(float* c, const uint32_t* a, const uint32_t* b) {
    asm volatile("mma.sync.aligned.m16n8k16.row.col.f32.f16.f16.f32 "
        "{%0,%1,%2,%3},{%4,%5,%6,%7},{%8,%9},{%0,%1,%2,%3};"
        : "+f"(c[0]), "+f"(c[1]), "+f"(c[2]), "+f"(c[3])
        : "r"(a[0]), "r"(a[1]), "r"(a[2]), "r"(a[3]), "r"(b[0]), "r"(b[1]));
}
__device__ __forceinline__ uint32_t packh(float a, float b) {
    __half2 t = __floats2half2_rn(a, b);
    return *reinterpret_cast<uint32_t*>(&t);
}
__device__ __forceinline__ uint32_t mulh2(uint32_t a, uint32_t b) {
    __half2 r = __hmul2(*reinterpret_cast<__half2*>(&a), *reinterpret_cast<__half2*>(&b));
    return *reinterpret_cast<uint32_t*>(&r);
}
__device__ __forceinline__ void redv2(float* addr, float v0, float v1) {
    asm volatile("red.global.add.v2.f32 [%0], {%1,%2};" :: "l"(addr), "f"(v0), "f"(v1) : "memory");
}
#define CPA16(dst, src) asm volatile("cp.async.cg.shared.global [%0], [%1], 16;" :: "r"(dst), "l"(src))
#define CPC()  asm volatile("cp.async.commit_group;" ::: "memory")
#define CPW0() asm volatile("cp.async.wait_group 0;" ::: "memory")

__global__ void zero_hist_k() { int i = blockIdx.x*256 + threadIdx.x; if (i < 2*NBUCK) g_hist[i] = 0; }
__global__ void zero_f_k(float* p, int n) { int i = blockIdx.x*256 + threadIdx.x; if (i < n) p[i] = 0.f; }
__device__ __forceinline__ int bucket_of(float d) {
    int b = (int)(d * (512.0f/30.0f));
    return min(max(b, 0), NBUCK-1);
}
__global__ void hist_k(const float* __restrict__ dist, int E) {
    __shared__ int lh[NBUCK];
    int tid = threadIdx.x;
    int per = (E + gridDim.x - 1) / gridDim.x;
    int lo = blockIdx.x * per, hi = min(E, lo + per);
    for (int i = tid; i < NBUCK; i += 512) lh[i] = 0;
    __syncthreads();
    for (int e = lo + tid; e < hi; e += 512) atomicAdd(&lh[bucket_of(dist[e])], 1);
    __syncthreads();
    for (int i = tid; i < NBUCK; i += 512) if (lh[i]) atomicAdd(&g_hist[i], lh[i]);
}
__global__ void scan512_k() {
    __shared__ int s[NBUCK];
    int tid = threadIdx.x;
    int v0 = g_hist[tid];
    s[tid] = v0; __syncthreads();
    for (int off = 1; off < NBUCK; off <<= 1) {
        int v = 0;
        if (tid >= off) v = s[tid - off];
        __syncthreads(); s[tid] += v; __syncthreads();
    }
    g_hist[NBUCK + tid] = s[tid] - v0;
}
__global__ void scatter_perm_k(const float* __restrict__ dist, int E) {
    __shared__ int lh[NBUCK], base[NBUCK];
    int tid = threadIdx.x;
    int per = (E + gridDim.x - 1) / gridDim.x;
    int lo = blockIdx.x * per, hi = min(E, lo + per);
    for (int i = tid; i < NBUCK; i += 512) lh[i] = 0;
    __syncthreads();
    for (int e = lo + tid; e < hi; e += 512) atomicAdd(&lh[bucket_of(dist[e])], 1);
    __syncthreads();
    for (int i = tid; i < NBUCK; i += 512)
        base[i] = lh[i] ? atomicAdd(&g_hist[NBUCK + i], lh[i]) : 0;
    __syncthreads();
    for (int i = tid; i < NBUCK; i += 512) lh[i] = 0;
    __syncthreads();
    for (int e = lo + tid; e < hi; e += 512) {
        int b = bucket_of(dist[e]);
        int r = atomicAdd(&lh[b], 1);
        g_perm[base[b] + r] = e;
    }
}
__global__ void init_h_k(const int* __restrict__ Z, const float* __restrict__ ne,
                         float* __restrict__ h, int N) {
    int idx = blockIdx.x*256 + threadIdx.x;
    if (idx < N*128) h[idx] = ne[Z[idx >> 7]*128 + (idx & 127)];
}
__global__ void conv_pad_k(const float* __restrict__ src, __half* __restrict__ dh,
                           int R, int Ks, int ld, int off, int Kpad, int tot) {
    int idx = blockIdx.x*256 + threadIdx.x;
    if (idx < tot) {
        int r = idx / Kpad, k = idx % Kpad;
        float v = (r < R && k < Ks) ? src[(size_t)r*ld + off + k] : 0.f;
        dh[idx] = __float2half_rn(v);
    }
}
__global__ void p_kernel(const float* __restrict__ edge_emb, const float* __restrict__ We1,
                         const float* __restrict__ be1, float* __restrict__ P) {
    int ty = blockIdx.x, layer = blockIdx.y, j = threadIdx.x;
    __shared__ float em[128];
    if (j < 128) em[j] = edge_emb[ty*128 + j];
    __syncthreads();
    if (j < 428) {
        const float* wrow = We1 + ((size_t)layer*428 + j)*428;
        float acc = be1[layer*428 + j];
        #pragma unroll 8
        for (int k = 0; k < 128; k++) acc = fmaf(em[k], wrow[k], acc);
        P[((size_t)layer*400 + ty)*428 + j] = acc;
    }
}
__global__ void rbf_klo_k(const float* __restrict__ dist, int E) {
    __shared__ float s[64];
    int tid = threadIdx.x, gr = blockIdx.x*64 + tid;
    s[tid] = dist[g_perm[min(gr, E-1)]];
    __syncthreads();
    for (int o = 32; o > 0; o >>= 1) {
        if (tid < o) s[tid] = fminf(s[tid], s[tid + o]);
        __syncthreads();
    }
    if (tid == 0) {
        int k = (int)floorf((s[0] - 1.055f) * RBF_INV);
        if (k < 0) k = 0;
        g_klo[blockIdx.x] = k & ~7;
    }
}
__global__ void rbf_split_k(const float* __restrict__ dist, int E) {
    int tid = threadIdx.x, gr = blockIdx.x*64 + tid;
    float d = dist[g_perm[min(gr, E-1)]];
    int k0 = g_klo[blockIdx.x];
    float vals[WK];
    #pragma unroll
    for (int i = 0; i < WK; i++) vals[i] = 0.f;
    int icen = (int)(d * RBF_INV) - k0;
    int ilo = max(0, icen - 10);
    int ihi = min(min(WK-1, icen + 10), 299 - k0);
    for (int i = ilo; i <= ihi; i++) {
        float x = d - (float)(k0 + i) * RBF_STEP;
        vals[i] = __expf(-RBF_INV * x * x);
    }
    size_t base = (size_t)gr * WK;
    #pragma unroll
    for (int i = 0; i < WK; i += 8) {
        uint4 H;
        H.x = packh(vals[i+0], vals[i+1]);
        H.y = packh(vals[i+2], vals[i+3]);
        H.z = packh(vals[i+4], vals[i+5]);
        H.w = packh(vals[i+6], vals[i+7]);
        *(uint4*)(g_rAh + base + i) = H;
    }
}

// ============ fused t -> ee kernel (round-14 proven) ============
__global__ void __launch_bounds__(256, 2)
fused_t_ee(const __half* __restrict__ W1, const __half* __restrict__ W2,
           const float* __restrict__ P, const float* __restrict__ be2,
           const int* __restrict__ etype, __half* __restrict__ ee, int E) {
    extern __shared__ char ds[];
    __shared__ int sety[64];
    __shared__ float sbias[128];
    int tid = threadIdx.x, lane = tid & 31, warp = tid >> 5, bx = blockIdx.x;
    int klo = g_klo[bx];
    if (tid < 64) sety[tid] = etype[g_perm[min(bx*64 + tid, E-1)]];
    if (tid < 128) sbias[tid] = be2[tid];
    uint32_t b0 = smem_u32(ds);
    uint32_t uTh = b0;
    uint32_t uAh = b0 + 5120;
    uint32_t uW1 = b0 + 10240;
    uint32_t uW2 = b0 + 15360;

    {
        int row = tid >> 2, kk = (tid & 3) << 3;
        CPA16(uAh + (uint32_t)(row*SLD + kk)*2, g_rAh + (size_t)(bx*64 + row)*WK + kk);
    }
    if (tid < 128) {
        int row = tid >> 2, kk = (tid & 3) << 3;
        CPA16(uW1 + (uint32_t)(row*SLD + kk)*2, W1 + (size_t)row*384 + klo + kk);
    }
    for (int i = tid; i < 512; i += 256) {
        int row = i >> 2, kk = (i & 3) * 8;
        CPA16(uW2 + (uint32_t)(row*SLD + kk)*2, W2 + (size_t)row*448 + kk);
    }
    CPC(); CPW0();
    __syncthreads();

    int arow = lane & 15, acol = (lane >> 4) << 3;
    int brow = (lane & 7) + ((lane >> 1) & 8), bcol = lane & 8;
    int r1 = (warp >> 1)*16, c1 = (warp & 1)*16;
    uint32_t a1off = (uint32_t)((r1 + arow)*SLD + acol)*2;
    uint32_t b1off = (uint32_t)((c1 + brow)*SLD + bcol)*2;
    int m0 = (warp >> 2)*32, n0 = (warp & 3)*32;
    uint32_t a2off[2];
    #pragma unroll
    for (int mi = 0; mi < 2; mi++) a2off[mi] = (uint32_t)((m0 + mi*16 + arow)*SLD + acol)*2;
    uint32_t b2off0 = (uint32_t)((n0 + brow)*SLD + bcol)*2;
    uint32_t b2off1 = (uint32_t)((n0 + 16 + brow)*SLD + bcol)*2;
    int lrow = lane >> 2, lcol = (lane & 3)*2;

    float eacc[2][4][4];
    #pragma unroll
    for (int mi = 0; mi < 2; mi++)
        #pragma unroll
        for (int ni = 0; ni < 4; ni++)
            #pragma unroll
            for (int q = 0; q < 4; q++) eacc[mi][ni][q] = 0.f;

    int buf = 0;
    for (int c = 0; c < 14; c++) {
        if (c < 13) {
            uint32_t cb = (uint32_t)(buf ^ 1);
            if (tid < 128) {
                int row = tid >> 2, kk = (tid & 3) << 3;
                CPA16(uW1 + cb*2560 + (uint32_t)(row*SLD + kk)*2,
                      W1 + (size_t)((c+1)*32 + row)*384 + klo + kk);
            }
            for (int i = tid; i < 512; i += 256) {
                int row = i >> 2, kk = (i & 3) * 8;
                CPA16(uW2 + cb*10240 + (uint32_t)(row*SLD + kk)*2,
                      W2 + (size_t)row*448 + (c+1)*32 + kk);
            }
            CPC();
        }
        float acc1[2][4];
        #pragma unroll
        for (int ni = 0; ni < 2; ni++)
            #pragma unroll
            for (int q = 0; q < 4; q++) acc1[ni][q] = 0.f;
        {
            uint32_t w1b = (uint32_t)buf * 2560;
            #pragma unroll
            for (int ks = 0; ks < 2; ks++) {
                uint32_t ah[4], bh[4];
                ldmx4(ah[0], ah[1], ah[2], ah[3], uAh + a1off + ks*32);
                ldmx4(bh[0], bh[1], bh[2], bh[3], uW1 + w1b + b1off + ks*32);
                #pragma unroll
                for (int ni = 0; ni < 2; ni++)
                    mma16816(acc1[ni], ah, &bh[ni*2]);
            }
        }
        {
            int gcb = c*32;
            #pragma unroll
            for (int half = 0; half < 2; half++) {
                int r = r1 + lrow + half*8;
                const float* Pr = P + (size_t)sety[r]*428;
                #pragma unroll
                for (int ni = 0; ni < 2; ni++) {
                    int col = c1 + ni*8 + lcol;
                    int gcol = gcb + col;
                    float v0 = 0.f, v1 = 0.f;
                    if (gcol < 428) {
                        float2 pv = *(const float2*)(Pr + gcol);
                        v0 = fmaxf(acc1[ni][half*2+0] + pv.x, 0.f);
                        v1 = fmaxf(acc1[ni][half*2+1] + pv.y, 0.f);
                    }
                    *(uint32_t*)(ds + (uint32_t)(r*SLD + col)*2) = packh(v0, v1);
                }
            }
        }
        __syncthreads();
        {
            uint32_t w2b = (uint32_t)buf * 10240;
            #pragma unroll
            for (int ks = 0; ks < 2; ks++) {
                uint32_t bh[8];
                ldmx4(bh[0], bh[1], bh[2], bh[3], uW2 + w2b + b2off0 + ks*32);
                ldmx4(bh[4], bh[5], bh[6], bh[7], uW2 + w2b + b2off1 + ks*32);
                #pragma unroll
                for (int mi = 0; mi < 2; mi++) {
                    uint32_t ah[4];
                    ldmx4(ah[0], ah[1], ah[2], ah[3], uTh + a2off[mi] + ks*32);
                    #pragma unroll
                    for (int ni = 0; ni < 4; ni++)
                        mma16816(eacc[mi][ni], ah, &bh[ni*2]);
                }
            }
        }
        if (c < 13) CPW0();
        __syncthreads();
        buf ^= 1;
    }

    int rowb = bx*64 + m0;
    #pragma unroll
    for (int mi = 0; mi < 2; mi++) {
        #pragma unroll
        for (int half = 0; half < 2; half++) {
            int row = rowb + mi*16 + lrow + half*8;
            if (row < E) {
                size_t cb = (size_t)row * 128;
                #pragma unroll
                for (int ni = 0; ni < 4; ni++) {
                    int col = n0 + ni*8 + lcol;
                    *(uint32_t*)(ee + cb + col) =
                        packh(eacc[mi][ni][half*2+0] + sbias[col],
                              eacc[mi][ni][half*2+1] + sbias[col+1]);
                }
            }
        }
    }
}

// ============ fused node MLP: tmp = (relu(h @ Wn1^T + b1)) @ Wn2^T + b2, fp16 out ============
// 64-node tiles, 4 chunks of 32 intermediate cols.
// smem: T 0..5120 (64x40), A 5120..22528 (64x136), W1 22528 (2x8704 = 32x136), W2 39936 (2x10240) = 60416
__global__ void __launch_bounds__(256, 2)
node_mlp_k(const float* __restrict__ h, const __half* __restrict__ W1,
           const __half* __restrict__ W2, const float* __restrict__ b1,
           const float* __restrict__ b2, __half* __restrict__ tmp, int N) {
    extern __shared__ char ds[];
    __shared__ float sb1[128], sb2[128];
    int tid = threadIdx.x, lane = tid & 31, warp = tid >> 5, bx = blockIdx.x;
    if (tid < 128) { sb1[tid] = b1[tid]; sb2[tid] = b2[tid]; }
    uint32_t b0 = smem_u32(ds);
    uint32_t uT  = b0;
    uint32_t uA  = b0 + 5120;
    uint32_t uW1 = b0 + 22528;
    uint32_t uW2 = b0 + 39936;

    // chunk-0 weights via cp.async
    for (int i = tid; i < 512; i += 256) {
        int r = i >> 4, kk = (i & 15) * 8;
        CPA16(uW1 + (uint32_t)(r*136 + kk)*2, W1 + (size_t)r*128 + kk);
    }
    for (int i = tid; i < 512; i += 256) {
        int r = i >> 2, kk = (i & 3) * 8;
        CPA16(uW2 + (uint32_t)(r*SLD + kk)*2, W2 + (size_t)r*128 + kk);
    }
    CPC();
    // A: 64 h-rows (fp32) -> fp16 smem, stride 136
    {
        int row = tid >> 2, cseg = (tid & 3) * 32;
        const float* hr = h + (size_t)min(bx*64 + row, N-1) * 128 + cseg;
        #pragma unroll
        for (int j = 0; j < 8; j++) {
            float4 f = *(const float4*)(hr + j*4);
            uint2 v;
            v.x = packh(f.x, f.y);
            v.y = packh(f.z, f.w);
            *(uint2*)(ds + 5120 + (uint32_t)(row*136 + cseg + j*4)*2) = v;
        }
    }
    CPW0();
    __syncthreads();

    int arow = lane & 15, acol = (lane >> 4) << 3;
    int brow = (lane & 7) + ((lane >> 1) & 8), bcol = lane & 8;
    int r1 = (warp >> 1)*16, c1 = (warp & 1)*16;
    uint32_t a1off = (uint32_t)((r1 + arow)*136 + acol)*2;
    uint32_t b1off = (uint32_t)((c1 + brow)*136 + bcol)*2;
    int m0 = (warp >> 2)*32, n0 = (warp & 3)*32;
    uint32_t a2off[2];
    #pragma unroll
    for (int mi = 0; mi < 2; mi++) a2off[mi] = (uint32_t)((m0 + mi*16 + arow)*SLD + acol)*2;
    uint32_t b2off0 = (uint32_t)((n0 + brow)*SLD + bcol)*2;
    uint32_t b2off1 = (uint32_t)((n0 + 16 + brow)*SLD + bcol)*2;
    int lrow = lane >> 2, lcol = (lane & 3)*2;

    float eacc[2][4][4];
    #pragma unroll
    for (int mi = 0; mi < 2; mi++)
        #pragma unroll
        for (int ni = 0; ni < 4; ni++)
            #pragma unroll
            for (int q = 0; q < 4; q++) eacc[mi][ni][q] = 0.f;

    int buf = 0;
    for (int c = 0; c < 4; c++) {
        if (c < 3) {
            uint32_t cb = (uint32_t)(buf ^ 1);
            for (int i = tid; i < 512; i += 256) {
                int r = i >> 4, kk = (i & 15) * 8;
                CPA16(uW1 + cb*8704 + (uint32_t)(r*136 + kk)*2,
                      W1 + (size_t)((c+1)*32 + r)*128 + kk);
            }
            for (int i = tid; i < 512; i += 256) {
                int r = i >> 2, kk = (i & 3) * 8;
                CPA16(uW2 + cb*10240 + (uint32_t)(r*SLD + kk)*2,
                      W2 + (size_t)r*128 + (c+1)*32 + kk);
            }
            CPC();
        }
        // MMA1: t1_chunk[64,32] = A[64,128] @ W1chunk^T, K=128
        float acc1[2][4];
        #pragma unroll
        for (int ni = 0; ni < 2; ni++)
            #pragma unroll
            for (int q = 0; q < 4; q++) acc1[ni][q] = 0.f;
        {
            uint32_t w1b = (uint32_t)buf * 8704;
            #pragma unroll
            for (int ks = 0; ks < 8; ks++) {
                uint32_t ah[4], bh[4];
                ldmx4(ah[0], ah[1], ah[2], ah[3], uA + a1off + ks*32);
                ldmx4(bh[0], bh[1], bh[2], bh[3], uW1 + w1b + b1off + ks*32);
                #pragma unroll
                for (int ni = 0; ni < 2; ni++)
                    mma16816(acc1[ni], ah, &bh[ni*2]);
            }
        }
        // epilogue1: +b1, relu, pack fp16 -> T
        {
            int gcb = c*32;
            #pragma unroll
            for (int half = 0; half < 2; half++) {
                int r = r1 + lrow + half*8;
                #pragma unroll
                for (int ni = 0; ni < 2; ni++) {
                    int col = c1 + ni*8 + lcol;
                    int gcol = gcb + col;
                    float v0 = fmaxf(acc1[ni][half*2+0] + sb1[gcol], 0.f);
                    float v1 = fmaxf(acc1[ni][half*2+1] + sb1[gcol+1], 0.f);
                    *(uint32_t*)(ds + (uint32_t)(r*SLD + col)*2) = packh(v0, v1);
                }
            }
        }
        __syncthreads();
        // MMA2: eacc += t1_chunk @ W2chunk^T, K=32
        {
            uint32_t w2b = (uint32_t)buf * 10240;
            #pragma unroll
            for (int ks = 0; ks < 2; ks++) {
                uint32_t bh[8];
                ldmx4(bh[0], bh[1], bh[2], bh[3], uW2 + w2b + b2off0 + ks*32);
                ldmx4(bh[4], bh[5], bh[6], bh[7], uW2 + w2b + b2off1 + ks*32);
                #pragma unroll
                for (int mi = 0; mi < 2; mi++) {
                    uint32_t ah[4];
                    ldmx4(ah[0], ah[1], ah[2], ah[3], uT + a2off[mi] + ks*32);
                    #pragma unroll
                    for (int ni = 0; ni < 4; ni++)
                        mma16816(eacc[mi][ni], ah, &bh[ni*2]);
                }
            }
        }
        if (c < 3) CPW0();
        __syncthreads();
        buf ^= 1;
    }

    int rowb = bx*64 + m0;
    #pragma unroll
    for (int mi = 0; mi < 2; mi++) {
        #pragma unroll
        for (int half = 0; half < 2; half++) {
            int row = rowb + mi*16 + lrow + half*8;
            if (row < N) {
                size_t cb = (size_t)row * 128;
                #pragma unroll
                for (int ni = 0; ni < 4; ni++) {
                    int col = n0 + ni*8 + lcol;
                    *(uint32_t*)(tmp + cb + col) =
                        packh(eacc[mi][ni][half*2+0] + sb2[col],
                              eacc[mi][ni][half*2+1] + sb2[col+1]);
                }
            }
        }
    }
}

// ============ generic pipelined GEMM (single fp16) ============
// EPI: 0 store fp16, 1 relu store fp16, 3 tanh + red.v2 scatter
// AIN: 0 fp32 rows (Af); 2 product A1[gidx[perm[row]]]*A2[row] (fp16)
template<int EPI, int AIN>
__global__ void __launch_bounds__(256)
gemm_mma(const float* __restrict__ Af, const __half* __restrict__ A1,
         const __half* __restrict__ A2, int lda, int Kloop,
         const __half* __restrict__ Bh, int Kpad,
         const float* __restrict__ bias, __half* __restrict__ C, int M,
         const int* __restrict__ gidx, const int* __restrict__ sidx, float* __restrict__ Hout) {
    extern __shared__ char ds[];
    __shared__ float sbias[128];
    int tid = threadIdx.x, lane = tid & 31, warp = tid >> 5;
    if (tid < 128) sbias[tid] = bias[tid];

    uint32_t b0 = smem_u32(ds);
    uint32_t uAh = b0, uBh = b0 + 2*BUFB;

    const float* pf[4];
    const __half *p1[4], *p2[4];
    #pragma unroll
    for (int i = 0; i < 4; i++) {
        int r = blockIdx.x*128 + i*32 + (tid >> 3);
        int rc = min(r, M-1);
        if (AIN == 0) pf[i] = Af + (size_t)rc * lda;
        else {
            p1[i] = A1 + (size_t)gidx[g_perm[rc]] * 128;
            p2[i] = A2 + (size_t)rc * 128;
        }
    }
    int akoff = (tid & 7) << 2;
    int ckoff = (tid & 3) << 3;
    int crow  = tid >> 2;
    uint32_t cdst0 = ((uint32_t)crow * SLD + ckoff) * 2;
    uint32_t cdst1 = ((uint32_t)(crow + 64) * SLD + ckoff) * 2;
    uint32_t asts[4];
    #pragma unroll
    for (int i = 0; i < 4; i++) asts[i] = ((uint32_t)(i*32 + (tid >> 3)) * SLD + akoff) * 2;

    int m0 = (warp >> 2) * 64, n0 = (warp & 3) * 32;
    int arow = lane & 15, acol = (lane >> 4) << 3;
    int brow = (lane & 7) + ((lane >> 1) & 8), bcol = lane & 8;
    uint32_t aoff[4];
    #pragma unroll
    for (int mi = 0; mi < 4; mi++) aoff[mi] = ((m0 + mi*16 + arow)*SLD + acol) * 2;
    uint32_t boff0 = ((n0 + brow)*SLD + bcol) * 2;
    uint32_t boff1 = ((n0 + 16 + brow)*SLD + bcol) * 2;

    float acc[4][4][4];
    #pragma unroll
    for (int mi = 0; mi < 4; mi++)
        #pragma unroll
        for (int ni = 0; ni < 4; ni++)
            #pragma unroll
            for (int q = 0; q < 4; q++) acc[mi][ni][q] = 0.f;

    uint2 rA[4];
    int nch = Kloop >> 5;

    {
        CPA16(uBh + cdst0, Bh + (size_t)crow * Kpad + ckoff);
        CPA16(uBh + cdst1, Bh + (size_t)(crow + 64) * Kpad + ckoff);
        CPC();
        #pragma unroll
        for (int i = 0; i < 4; i++) {
            if (AIN == 0) {
                float4 f = *(const float4*)(pf[i] + akoff);
                rA[i].x = packh(f.x, f.y);
                rA[i].y = packh(f.z, f.w);
            } else {
                uint2 a = *(const uint2*)(p1[i] + akoff);
                uint2 b = *(const uint2*)(p2[i] + akoff);
                rA[i].x = mulh2(a.x, b.x);
                rA[i].y = mulh2(a.y, b.y);
            }
        }
        #pragma unroll
        for (int i = 0; i < 4; i++) *(uint2*)(ds + asts[i]) = rA[i];
        CPW0();
        __syncthreads();
    }

    int buf = 0;
    for (int c = 0; c < nch; c++) {
        int k1 = (c + 1) << 5;
        bool more = (c + 1) < nch;
        if (more) {
            uint32_t bb = (uint32_t)(buf ^ 1) * BUFB;
            CPA16(uBh + bb + cdst0, Bh + (size_t)crow * Kpad + k1 + ckoff);
            CPA16(uBh + bb + cdst1, Bh + (size_t)(crow + 64) * Kpad + k1 + ckoff);
            CPC();
            #pragma unroll
            for (int i = 0; i < 4; i++) {
                if (AIN == 0) {
                    float4 f = *(const float4*)(pf[i] + k1 + akoff);
                    rA[i].x = packh(f.x, f.y);
                    rA[i].y = packh(f.z, f.w);
                } else {
                    uint2 a = *(const uint2*)(p1[i] + k1 + akoff);
                    uint2 b = *(const uint2*)(p2[i] + k1 + akoff);
                    rA[i].x = mulh2(a.x, b.x);
                    rA[i].y = mulh2(a.y, b.y);
                }
            }
        }
        {
            uint32_t bb = (uint32_t)buf * BUFB;
            #pragma unroll
            for (int ks = 0; ks < 2; ks++) {
                uint32_t bh[8];
                ldmx4(bh[0], bh[1], bh[2], bh[3], uBh + bb + boff0 + ks*32);
                ldmx4(bh[4], bh[5], bh[6], bh[7], uBh + bb + boff1 + ks*32);
                #pragma unroll
                for (int mi = 0; mi < 4; mi++) {
                    uint32_t ah[4];
                    ldmx4(ah[0], ah[1], ah[2], ah[3], uAh + bb + aoff[mi] + ks*32);
                    #pragma unroll
                    for (int ni = 0; ni < 4; ni++)
                        mma16816(acc[mi][ni], ah, &bh[ni*2]);
                }
            }
        }
        if (more) {
            uint32_t bb = (uint32_t)(buf ^ 1) * BUFB;
            #pragma unroll
            for (int i = 0; i < 4; i++) *(uint2*)(ds + bb + asts[i]) = rA[i];
            CPW0();
            __syncthreads();
            buf ^= 1;
        }
    }

    int rowb = blockIdx.x*128 + m0;
    #pragma unroll
    for (int mi = 0; mi < 4; mi++) {
        #pragma unroll
        for (int half = 0; half < 2; half++) {
            int row = rowb + mi*16 + (lane >> 2) + half*8;
            if (row < M) {
                if (EPI == 3) {
                    int dg = sidx[g_perm[row]];
                    float* Hr = Hout + (size_t)dg * 128;
                    #pragma unroll
                    for (int ni = 0; ni < 4; ni++) {
                        int col = n0 + ni*8 + (lane & 3)*2;
                        float v0 = tanhf(acc[mi][ni][half*2+0] + sbias[col]);
                        float v1 = tanhf(acc[mi][ni][half*2+1] + sbias[col+1]);
                        redv2(Hr + col, v0, v1);
                    }
                } else {
                    size_t cb = (size_t)row * 128;
                    #pragma unroll
                    for (int ni = 0; ni < 4; ni++) {
                        int col = n0 + ni*8 + (lane & 3)*2;
                        float v0 = acc[mi][ni][half*2+0] + sbias[col];
                        float v1 = acc[mi][ni][half*2+1] + sbias[col+1];
                        if (EPI == 1) { v0 = fmaxf(v0, 0.f); v1 = fmaxf(v1, 0.f); }
                        *(uint32_t*)(C + cb + col) = packh(v0, v1);
                    }
                }
            }
        }
    }
}

__global__ void readout2_k(const __half* __restrict__ rr, const float* __restrict__ Wr2,
                           const float* __restrict__ br2, const int* __restrict__ gid,
                           float* __restrict__ out, int N) {
    __shared__ float w[128];
    int tid = threadIdx.x;
    if (tid < 128) w[tid] = Wr2[tid];
    __syncthreads();
    int warp = tid >> 5, lane = tid & 31;
    int n = blockIdx.x*4 + warp;
    if (n >= N) return;
    const __half* hr = rr + (size_t)n * 128;
    float s = 0.f;
    #pragma unroll
    for (int i = 0; i < 4; i++) s = fmaf(__half2float(hr[lane + i*32]), w[lane + i*32], s);
    #pragma unroll
    for (int o = 16; o > 0; o >>= 1) s += __shfl_down_sync(0xffffffffu, s, o);
    if (lane == 0) atomicAdd(&out[gid[n]], s + br2[0]);
}

extern "C" void kernel_launch(void* const* d_in, const int* in_sizes, int n_in,
                              void* d_out, int out_size) {
    const int*   Z     = (const int*)  d_in[0];
    const int*   etype = (const int*)  d_in[1];
    const float* dist  = (const float*)d_in[2];
    const int*   src   = (const int*)  d_in[3];
    const int*   dst   = (const int*)  d_in[4];
    const int*   gid   = (const int*)  d_in[5];
    const float* node_emb = (const float*)d_in[6];
    const float* edge_emb = (const float*)d_in[7];
    const float* Wn1 = (const float*)d_in[8];
    const float* bn1 = (const float*)d_in[9];
    const float* Wn2 = (const float*)d_in[10];
    const float* bn2 = (const float*)d_in[11];
    const float* We1 = (const float*)d_in[12];
    const float* be1 = (const float*)d_in[13];
    const float* We2 = (const float*)d_in[14];
    const float* be2 = (const float*)d_in[15];
    const float* Wc  = (const float*)d_in[16];
    const float* bc  = (const float*)d_in[17];
    const float* Wr1 = (const float*)d_in[18];
    const float* br1 = (const float*)d_in[19];
    const float* Wr2 = (const float*)d_in[20];
    const float* br2 = (const float*)d_in[21];

    int N = in_sizes[0], E = in_sizes[1], G = out_size;
    float* out = (float*)d_out;

    static cudaStream_t s1 = 0, s2 = 0;
    static cudaEvent_t evF, evRBF, evA[3], evB[3], evC[3];
    static bool sinit = false;
    if (!sinit) {
        cudaStreamCreateWithFlags(&s1, cudaStreamNonBlocking);
        cudaStreamCreateWithFlags(&s2, cudaStreamNonBlocking);
        cudaEventCreateWithFlags(&evF,   cudaEventDisableTiming);
        cudaEventCreateWithFlags(&evRBF, cudaEventDisableTiming);
        for (int i = 0; i < 3; i++) {
            cudaEventCreateWithFlags(&evA[i], cudaEventDisableTiming);
            cudaEventCreateWithFlags(&evB[i], cudaEventDisableTiming);
            cudaEventCreateWithFlags(&evC[i], cudaEventDisableTiming);
        }
        cudaFuncSetAttribute((const void*)fused_t_ee,    cudaFuncAttributeMaxDynamicSharedMemorySize, DSMEM4);
        cudaFuncSetAttribute((const void*)node_mlp_k,    cudaFuncAttributeMaxDynamicSharedMemorySize, DSMEM5);
        cudaFuncSetAttribute((const void*)gemm_mma<1,0>, cudaFuncAttributeMaxDynamicSharedMemorySize, DSMEM2);
        cudaFuncSetAttribute((const void*)gemm_mma<3,2>, cudaFuncAttributeMaxDynamicSharedMemorySize, DSMEM2);
        sinit = true;
    }

    void* p;
    float *h, *P;
    __half *ee, *tmp;
    __half *W1h,*We2h,*Wn1h,*Wn2h,*Wch,*Wr1h;
    cudaGetSymbolAddress(&p, g_h);   h   = (float*)p;
    cudaGetSymbolAddress(&p, g_ee);  ee  = (__half*)p;
    cudaGetSymbolAddress(&p, g_tmp); tmp = (__half*)p;
    cudaGetSymbolAddress(&p, g_P);   P   = (float*)p;
    cudaGetSymbolAddress(&p, g_W1h);  W1h  = (__half*)p;
    cudaGetSymbolAddress(&p, g_We2h); We2h = (__half*)p;
    cudaGetSymbolAddress(&p, g_Wn1h); Wn1h = (__half*)p;
    cudaGetSymbolAddress(&p, g_Wn2h); Wn2h = (__half*)p;
    cudaGetSymbolAddress(&p, g_Wch);  Wch  = (__half*)p;
    cudaGetSymbolAddress(&p, g_Wr1h); Wr1h = (__half*)p;

    int gE = (E + 127)/128, gE2 = (E + 63)/64, gN = (N + 127)/128, gN2 = (N + 63)/64;

    cudaEventRecord(evF, 0);
    cudaStreamWaitEvent(s1, evF, 0);
    cudaStreamWaitEvent(s2, evF, 0);

    // main: sort + rbf chain
    zero_hist_k<<<(2*NBUCK + 255)/256, 256>>>();
    hist_k<<<148, 512>>>(dist, E);
    scan512_k<<<1, NBUCK>>>();
    scatter_perm_k<<<148, 512>>>(dist, E);
    rbf_klo_k<<<gE2, 64>>>(dist, E);
    rbf_split_k<<<gE2, 64>>>(dist, E);
    cudaEventRecord(evRBF, 0);

    // s1: node-side prep
    init_h_k<<<(N*128 + 255)/256, 256, 0, s1>>>(Z, node_emb, h, N);
    for (int i = 0; i < 3; i++) {
        conv_pad_k<<<(128*128 + 255)/256, 256, 0, s1>>>(Wn1 + (size_t)i*128*128, Wn1h + (size_t)i*128*128, 128, 128, 128, 0, 128, 128*128);
        conv_pad_k<<<(128*128 + 255)/256, 256, 0, s1>>>(Wn2 + (size_t)i*128*128, Wn2h + (size_t)i*128*128, 128, 128, 128, 0, 128, 128*128);
    }
    conv_pad_k<<<(128*128 + 255)/256, 256, 0, s1>>>(Wr1, Wr1h, 128, 128, 128, 0, 128, 128*128);

    // s2: edge-side prep
    for (int i = 0; i < 3; i++) {
        conv_pad_k<<<(512*384 + 255)/256, 256, 0, s2>>>(We1 + (size_t)i*428*428, W1h + (size_t)i*512*384, 428, 300, 428, 128, 384, 512*384);
        conv_pad_k<<<(128*448 + 255)/256, 256, 0, s2>>>(We2 + (size_t)i*128*428, We2h + (size_t)i*128*448, 128, 428, 428, 0, 448, 128*448);
        conv_pad_k<<<(128*128 + 255)/256, 256, 0, s2>>>(Wc  + (size_t)i*128*128, Wch  + (size_t)i*128*128, 128, 128, 128, 0, 128, 128*128);
    }
    p_kernel<<<dim3(400, 3), 448, 0, s2>>>(edge_emb, We1, be1, P);
    cudaStreamWaitEvent(s2, evRBF, 0);

    for (int i = 0; i < 3; i++) {
        __half* eeb = ee + (size_t)(i & 1) * E_MAXE * 128;
        if (i >= 2) cudaStreamWaitEvent(s2, evC[i-2], 0);
        fused_t_ee<<<gE2, 256, DSMEM4, s2>>>(W1h + (size_t)i*512*384,
                                             We2h + (size_t)i*128*448,
                                             P + (size_t)i*400*428, be2 + i*128, etype, eeb, E);
        cudaEventRecord(evB[i], s2);

        if (i >= 1) cudaStreamWaitEvent(s1, evC[i-1], 0);
        node_mlp_k<<<gN2, 256, DSMEM5, s1>>>(h,
            Wn1h + (size_t)i*128*128, Wn2h + (size_t)i*128*128,
            bn1 + i*128, bn2 + i*128, tmp, N);
        cudaEventRecord(evA[i], s1);

        cudaStreamWaitEvent(0, evA[i], 0);
        cudaStreamWaitEvent(0, evB[i], 0);
        gemm_mma<3,2><<<gE, 256, DSMEM2, 0>>>(nullptr, tmp, eeb, 128, 128,
            Wch + (size_t)i*128*128, 128,
            bc + i*128, nullptr, E, src, dst, h);
        cudaEventRecord(evC[i], 0);
    }

    gemm_mma<1,0><<<gN, 256, DSMEM2, 0>>>(h, nullptr, nullptr, 128, 128,
        Wr1h, 128, br1, tmp, N, nullptr, nullptr, nullptr);
    zero_f_k<<<(G + 255)/256, 256>>>(out, G);
    readout2_k<<<(N + 3)/4, 128>>>(tmp, Wr2, br2, gid, out, N);
}

// round 16
// speedup vs baseline: 1.0244x; 1.0244x over previous
#include <cuda_runtime.h>
#include <cuda_fp16.h>
#include <math.h>
#include <stdint.h>

#define N_RBF 300
#define NBUCK 512
#define N_MAXN 100352
#define E_MAXE 400384
#define GE2_MAX 6256
#define RBF_STEP (30.0f/299.0f)
#define RBF_INV  (299.0f/30.0f)
#define SLD 40
#define WK 32
#define BUFB 10240
#define DSMEM2 40960
#define DSMEM4 35840

__device__ float  g_h  [(size_t)N_MAXN*128];
__device__ __half g_ee [2*(size_t)E_MAXE*128];
__device__ __half g_tmp[(size_t)N_MAXN*128];
__device__ float  g_P  [3*400*428];
__device__ int    g_perm[E_MAXE];
__device__ int    g_hist[2*NBUCK];
__device__ int    g_klo [GE2_MAX];
__device__ __half g_rAh[(size_t)E_MAXE*WK];
__device__ __half g_W1h[3*512*384];
__device__ __half g_We2h[3*128*448];
__device__ __half g_Wn1h[3*128*128];
__device__ __half g_Wn2h[3*128*128];
__device__ __half g_Wch [3*128*128];
__device__ __half g_Wr1h[128*128];

__device__ __forceinline__ uint32_t smem_u32(const void* p) {
    uint32_t a;
    asm("{ .reg .u64 t; cvta.to.shared.u64 t, %1; cvt.u32.u64 %0, t; }" : "=r"(a) : "l"(p));
    return a;
}
__device__ __forceinline__ void ldmx4(uint32_t& r0, uint32_t& r1, uint32_t& r2, uint32_t& r3, uint32_t a) {
    asm volatile("ldmatrix.sync.aligned.m8n8.x4.shared.b16 {%0,%1,%2,%3}, [%4];"
        : "=r"(r0), "=r"(r1), "=r"(r2), "=r"(r3) : "r"(a));
}
__device__ __forceinline__ void mma16816(float* c, const uint32_t* a, const uint32_t* b) {
    asm volatile("mma.sync.aligned.m16n8k16.row.col.f32.f16.f16.f32 "
        "{%0,%1,%2,%3},{%4,%5,%6,%7},{%8,%9},{%0,%1,%2,%3};"
        : "+f"(c[0]), "+f"(c[1]), "+f"(c[2]), "+f"(c[3])
        : "r"(a[0]), "r"(a[1]), "r"(a[2]), "r"(a[3]), "r"(b[0]), "r"(b[1]));
}
__device__ __forceinline__ uint32_t packh(float a, float b) {
    __half2 t = __floats2half2_rn(a, b);
    return *reinterpret_cast<uint32_t*>(&t);
}
__device__ __forceinline__ uint32_t mulh2(uint32_t a, uint32_t b) {
    __half2 r = __hmul2(*reinterpret_cast<__half2*>(&a), *reinterpret_cast<__half2*>(&b));
    return *reinterpret_cast<uint32_t*>(&r);
}
__device__ __forceinline__ void redv2(float* addr, float v0, float v1) {
    asm volatile("red.global.add.v2.f32 [%0], {%1,%2};" :: "l"(addr), "f"(v0), "f"(v1) : "memory");
}
#define CPA16(dst, src) asm volatile("cp.async.cg.shared.global [%0], [%1], 16;" :: "r"(dst), "l"(src))
#define CPC()  asm volatile("cp.async.commit_group;" ::: "memory")
#define CPW0() asm volatile("cp.async.wait_group 0;" ::: "memory")

__global__ void zero_hist_k() { int i = blockIdx.x*256 + threadIdx.x; if (i < 2*NBUCK) g_hist[i] = 0; }
__global__ void zero_f_k(float* p, int n) { int i = blockIdx.x*256 + threadIdx.x; if (i < n) p[i] = 0.f; }
__device__ __forceinline__ int bucket_of(float d) {
    int b = (int)(d * (512.0f/30.0f));
    return min(max(b, 0), NBUCK-1);
}
__global__ void hist_k(const float* __restrict__ dist, int E) {
    __shared__ int lh[NBUCK];
    int tid = threadIdx.x;
    int per = (E + gridDim.x - 1) / gridDim.x;
    int lo = blockIdx.x * per, hi = min(E, lo + per);
    for (int i = tid; i < NBUCK; i += 512) lh[i] = 0;
    __syncthreads();
    for (int e = lo + tid; e < hi; e += 512) atomicAdd(&lh[bucket_of(dist[e])], 1);
    __syncthreads();
    for (int i = tid; i < NBUCK; i += 512) if (lh[i]) atomicAdd(&g_hist[i], lh[i]);
}
__global__ void scan512_k() {
    __shared__ int s[NBUCK];
    int tid = threadIdx.x;
    int v0 = g_hist[tid];
    s[tid] = v0; __syncthreads();
    for (int off = 1; off < NBUCK; off <<= 1) {
        int v = 0;
        if (tid >= off) v = s[tid - off];
        __syncthreads(); s[tid] += v; __syncthreads();
    }
    g_hist[NBUCK + tid] = s[tid] - v0;
}
__global__ void scatter_perm_k(const float* __restrict__ dist, int E) {
    __shared__ int lh[NBUCK], base[NBUCK];
    int tid = threadIdx.x;
    int per = (E + gridDim.x - 1) / gridDim.x;
    int lo = blockIdx.x * per, hi = min(E, lo + per);
    for (int i = tid; i < NBUCK; i += 512) lh[i] = 0;
    __syncthreads();
    for (int e = lo + tid; e < hi; e += 512) atomicAdd(&lh[bucket_of(dist[e])], 1);
    __syncthreads();
    for (int i = tid; i < NBUCK; i += 512)
        base[i] = lh[i] ? atomicAdd(&g_hist[NBUCK + i], lh[i]) : 0;
    __syncthreads();
    for (int i = tid; i < NBUCK; i += 512) lh[i] = 0;
    __syncthreads();
    for (int e = lo + tid; e < hi; e += 512) {
        int b = bucket_of(dist[e]);
        int r = atomicAdd(&lh[b], 1);
        g_perm[base[b] + r] = e;
    }
}
__global__ void init_h_k(const int* __restrict__ Z, const float* __restrict__ ne,
                         float* __restrict__ h, int N) {
    int idx = blockIdx.x*256 + threadIdx.x;
    if (idx < N*128) h[idx] = ne[Z[idx >> 7]*128 + (idx & 127)];
}
__global__ void conv_pad_k(const float* __restrict__ src, __half* __restrict__ dh,
                           int R, int Ks, int ld, int off, int Kpad, int tot) {
    int idx = blockIdx.x*256 + threadIdx.x;
    if (idx < tot) {
        int r = idx / Kpad, k = idx % Kpad;
        float v = (r < R && k < Ks) ? src[(size_t)r*ld + off + k] : 0.f;
        dh[idx] = __float2half_rn(v);
    }
}
__global__ void p_kernel(const float* __restrict__ edge_emb, const float* __restrict__ We1,
                         const float* __restrict__ be1, float* __restrict__ P) {
    int ty = blockIdx.x, layer = blockIdx.y, j = threadIdx.x;
    __shared__ float em[128];
    if (j < 128) em[j] = edge_emb[ty*128 + j];
    __syncthreads();
    if (j < 428) {
        const float* wrow = We1 + ((size_t)layer*428 + j)*428;
        float acc = be1[layer*428 + j];
        #pragma unroll 8
        for (int k = 0; k < 128; k++) acc = fmaf(em[k], wrow[k], acc);
        P[((size_t)layer*400 + ty)*428 + j] = acc;
    }
}
__global__ void rbf_klo_k(const float* __restrict__ dist, int E) {
    __shared__ float s[64];
    int tid = threadIdx.x, gr = blockIdx.x*64 + tid;
    s[tid] = dist[g_perm[min(gr, E-1)]];
    __syncthreads();
    for (int o = 32; o > 0; o >>= 1) {
        if (tid < o) s[tid] = fminf(s[tid], s[tid + o]);
        __syncthreads();
    }
    if (tid == 0) {
        int k = (int)floorf((s[0] - 1.055f) * RBF_INV);
        if (k < 0) k = 0;
        g_klo[blockIdx.x] = k & ~7;
    }
}
__global__ void rbf_split_k(const float* __restrict__ dist, int E) {
    int tid = threadIdx.x, gr = blockIdx.x*64 + tid;
    float d = dist[g_perm[min(gr, E-1)]];
    int k0 = g_klo[blockIdx.x];
    float vals[WK];
    #pragma unroll
    for (int i = 0; i < WK; i++) vals[i] = 0.f;
    int icen = (int)(d * RBF_INV) - k0;
    int ilo = max(0, icen - 10);
    int ihi = min(min(WK-1, icen + 10), 299 - k0);
    for (int i = ilo; i <= ihi; i++) {
        float x = d - (float)(k0 + i) * RBF_STEP;
        vals[i] = __expf(-RBF_INV * x * x);
    }
    size_t base = (size_t)gr * WK;
    #pragma unroll
    for (int i = 0; i < WK; i += 8) {
        uint4 H;
        H.x = packh(vals[i+0], vals[i+1]);
        H.y = packh(vals[i+2], vals[i+3]);
        H.z = packh(vals[i+4], vals[i+5]);
        H.w = packh(vals[i+6], vals[i+7]);
        *(uint4*)(g_rAh + base + i) = H;
    }
}

// ============ fused t -> ee kernel (round-14 proven) ============
__global__ void __launch_bounds__(256, 2)
fused_t_ee(const __half* __restrict__ W1, const __half* __restrict__ W2,
           const float* __restrict__ P, const float* __restrict__ be2,
           const int* __restrict__ etype, __half* __restrict__ ee, int E) {
    extern __shared__ char ds[];
    __shared__ int sety[64];
    __shared__ float sbias[128];
    int tid = threadIdx.x, lane = tid & 31, warp = tid >> 5, bx = blockIdx.x;
    int klo = g_klo[bx];
    if (tid < 64) sety[tid] = etype[g_perm[min(bx*64 + tid, E-1)]];
    if (tid < 128) sbias[tid] = be2[tid];
    uint32_t b0 = smem_u32(ds);
    uint32_t uTh = b0;
    uint32_t uAh = b0 + 5120;
    uint32_t uW1 = b0 + 10240;
    uint32_t uW2 = b0 + 15360;

    {
        int row = tid >> 2, kk = (tid & 3) << 3;
        CPA16(uAh + (uint32_t)(row*SLD + kk)*2, g_rAh + (size_t)(bx*64 + row)*WK + kk);
    }
    if (tid < 128) {
        int row = tid >> 2, kk = (tid & 3) << 3;
        CPA16(uW1 + (uint32_t)(row*SLD + kk)*2, W1 + (size_t)row*384 + klo + kk);
    }
    for (int i = tid; i < 512; i += 256) {
        int row = i >> 2, kk = (i & 3) * 8;
        CPA16(uW2 + (uint32_t)(row*SLD + kk)*2, W2 + (size_t)row*448 + kk);
    }
    CPC(); CPW0();
    __syncthreads();

    int arow = lane & 15, acol = (lane >> 4) << 3;
    int brow = (lane & 7) + ((lane >> 1) & 8), bcol = lane & 8;
    int r1 = (warp >> 1)*16, c1 = (warp & 1)*16;
    uint32_t a1off = (uint32_t)((r1 + arow)*SLD + acol)*2;
    uint32_t b1off = (uint32_t)((c1 + brow)*SLD + bcol)*2;
    int m0 = (warp >> 2)*32, n0 = (warp & 3)*32;
    uint32_t a2off[2];
    #pragma unroll
    for (int mi = 0; mi < 2; mi++) a2off[mi] = (uint32_t)((m0 + mi*16 + arow)*SLD + acol)*2;
    uint32_t b2off0 = (uint32_t)((n0 + brow)*SLD + bcol)*2;
    uint32_t b2off1 = (uint32_t)((n0 + 16 + brow)*SLD + bcol)*2;
    int lrow = lane >> 2, lcol = (lane & 3)*2;

    float eacc[2][4][4];
    #pragma unroll
    for (int mi = 0; mi < 2; mi++)
        #pragma unroll
        for (int ni = 0; ni < 4; ni++)
            #pragma unroll
            for (int q = 0; q < 4; q++) eacc[mi][ni][q] = 0.f;

    int buf = 0;
    for (int c = 0; c < 14; c++) {
        if (c < 13) {
            uint32_t cb = (uint32_t)(buf ^ 1);
            if (tid < 128) {
                int row = tid >> 2, kk = (tid & 3) << 3;
                CPA16(uW1 + cb*2560 + (uint32_t)(row*SLD + kk)*2,
                      W1 + (size_t)((c+1)*32 + row)*384 + klo + kk);
            }
            for (int i = tid; i < 512; i += 256) {
                int row = i >> 2, kk = (i & 3) * 8;
                CPA16(uW2 + cb*10240 + (uint32_t)(row*SLD + kk)*2,
                      W2 + (size_t)row*448 + (c+1)*32 + kk);
            }
            CPC();
        }
        float acc1[2][4];
        #pragma unroll
        for (int ni = 0; ni < 2; ni++)
            #pragma unroll
            for (int q = 0; q < 4; q++) acc1[ni][q] = 0.f;
        {
            uint32_t w1b = (uint32_t)buf * 2560;
            #pragma unroll
            for (int ks = 0; ks < 2; ks++) {
                uint32_t ah[4], bh[4];
                ldmx4(ah[0], ah[1], ah[2], ah[3], uAh + a1off + ks*32);
                ldmx4(bh[0], bh[1], bh[2], bh[3], uW1 + w1b + b1off + ks*32);
                #pragma unroll
                for (int ni = 0; ni < 2; ni++)
                    mma16816(acc1[ni], ah, &bh[ni*2]);
            }
        }
        {
            int gcb = c*32;
            #pragma unroll
            for (int half = 0; half < 2; half++) {
                int r = r1 + lrow + half*8;
                const float* Pr = P + (size_t)sety[r]*428;
                #pragma unroll
                for (int ni = 0; ni < 2; ni++) {
                    int col = c1 + ni*8 + lcol;
                    int gcol = gcb + col;
                    float v0 = 0.f, v1 = 0.f;
                    if (gcol < 428) {
                        float2 pv = *(const float2*)(Pr + gcol);
                        v0 = fmaxf(acc1[ni][half*2+0] + pv.x, 0.f);
                        v1 = fmaxf(acc1[ni][half*2+1] + pv.y, 0.f);
                    }
                    *(uint32_t*)(ds + (uint32_t)(r*SLD + col)*2) = packh(v0, v1);
                }
            }
        }
        __syncthreads();
        {
            uint32_t w2b = (uint32_t)buf * 10240;
            #pragma unroll
            for (int ks = 0; ks < 2; ks++) {
                uint32_t bh[8];
                ldmx4(bh[0], bh[1], bh[2], bh[3], uW2 + w2b + b2off0 + ks*32);
                ldmx4(bh[4], bh[5], bh[6], bh[7], uW2 + w2b + b2off1 + ks*32);
                #pragma unroll
                for (int mi = 0; mi < 2; mi++) {
                    uint32_t ah[4];
                    ldmx4(ah[0], ah[1], ah[2], ah[3], uTh + a2off[mi] + ks*32);
                    #pragma unroll
                    for (int ni = 0; ni < 4; ni++)
                        mma16816(eacc[mi][ni], ah, &bh[ni*2]);
                }
            }
        }
        if (c < 13) CPW0();
        __syncthreads();
        buf ^= 1;
    }

    int rowb = bx*64 + m0;
    #pragma unroll
    for (int mi = 0; mi < 2; mi++) {
        #pragma unroll
        for (int half = 0; half < 2; half++) {
            int row = rowb + mi*16 + lrow + half*8;
            if (row < E) {
                size_t cb = (size_t)row * 128;
                #pragma unroll
                for (int ni = 0; ni < 4; ni++) {
                    int col = n0 + ni*8 + lcol;
                    *(uint32_t*)(ee + cb + col) =
                        packh(eacc[mi][ni][half*2+0] + sbias[col],
                              eacc[mi][ni][half*2+1] + sbias[col+1]);
                }
            }
        }
    }
}

// ============ generic pipelined GEMM (single fp16) ============
// EPI: 0 store fp16, 1 relu store fp16, 3 tanh + red.v2 scatter,
//      4 readout: dot(relu(acc+bias), W2r) + br2 -> atomicAdd out[sidx[row]]
// AIN: 0 fp32 rows (Af); 1 fp16 rows (A1); 2 product A1[gidx[perm[row]]]*A2[row]
template<int EPI, int AIN>
__global__ void __launch_bounds__(256)
gemm_mma(const float* __restrict__ Af, const __half* __restrict__ A1,
         const __half* __restrict__ A2, int lda, int Kloop,
         const __half* __restrict__ Bh, int Kpad,
         const float* __restrict__ bias, __half* __restrict__ C, int M,
         const int* __restrict__ gidx, const int* __restrict__ sidx, float* __restrict__ Hout,
         const float* __restrict__ W2r, const float* __restrict__ br2p) {
    extern __shared__ char ds[];
    __shared__ float sbias[128];
    __shared__ float sw2[128];
    __shared__ float srow[128];
    int tid = threadIdx.x, lane = tid & 31, warp = tid >> 5;
    if (tid < 128) {
        sbias[tid] = bias[tid];
        if (EPI == 4) { sw2[tid] = W2r[tid]; srow[tid] = 0.f; }
    }

    uint32_t b0 = smem_u32(ds);
    uint32_t uAh = b0, uBh = b0 + 2*BUFB;

    const float* pf[4];
    const __half *p1[4], *p2[4];
    #pragma unroll
    for (int i = 0; i < 4; i++) {
        int r = blockIdx.x*128 + i*32 + (tid >> 3);
        int rc = min(r, M-1);
        if (AIN == 0) pf[i] = Af + (size_t)rc * lda;
        else if (AIN == 1) p1[i] = A1 + (size_t)rc * lda;
        else {
            p1[i] = A1 + (size_t)gidx[g_perm[rc]] * 128;
            p2[i] = A2 + (size_t)rc * 128;
        }
    }
    int akoff = (tid & 7) << 2;
    int ckoff = (tid & 3) << 3;
    int crow  = tid >> 2;
    uint32_t cdst0 = ((uint32_t)crow * SLD + ckoff) * 2;
    uint32_t cdst1 = ((uint32_t)(crow + 64) * SLD + ckoff) * 2;
    uint32_t asts[4];
    #pragma unroll
    for (int i = 0; i < 4; i++) asts[i] = ((uint32_t)(i*32 + (tid >> 3)) * SLD + akoff) * 2;

    int m0 = (warp >> 2) * 64, n0 = (warp & 3) * 32;
    int arow = lane & 15, acol = (lane >> 4) << 3;
    int brow = (lane & 7) + ((lane >> 1) & 8), bcol = lane & 8;
    uint32_t aoff[4];
    #pragma unroll
    for (int mi = 0; mi < 4; mi++) aoff[mi] = ((m0 + mi*16 + arow)*SLD + acol) * 2;
    uint32_t boff0 = ((n0 + brow)*SLD + bcol) * 2;
    uint32_t boff1 = ((n0 + 16 + brow)*SLD + bcol) * 2;

    float acc[4][4][4];
    #pragma unroll
    for (int mi = 0; mi < 4; mi++)
        #pragma unroll
        for (int ni = 0; ni < 4; ni++)
            #pragma unroll
            for (int q = 0; q < 4; q++) acc[mi][ni][q] = 0.f;

    uint2 rA[4];
    int nch = Kloop >> 5;

    {
        CPA16(uBh + cdst0, Bh + (size_t)crow * Kpad + ckoff);
        CPA16(uBh + cdst1, Bh + (size_t)(crow + 64) * Kpad + ckoff);
        CPC();
        #pragma unroll
        for (int i = 0; i < 4; i++) {
            if (AIN == 0) {
                float4 f = *(const float4*)(pf[i] + akoff);
                rA[i].x = packh(f.x, f.y);
                rA[i].y = packh(f.z, f.w);
            } else if (AIN == 1) {
                rA[i] = *(const uint2*)(p1[i] + akoff);
            } else {
                uint2 a = *(const uint2*)(p1[i] + akoff);
                uint2 b = *(const uint2*)(p2[i] + akoff);
                rA[i].x = mulh2(a.x, b.x);
                rA[i].y = mulh2(a.y, b.y);
            }
        }
        #pragma unroll
        for (int i = 0; i < 4; i++) *(uint2*)(ds + asts[i]) = rA[i];
        CPW0();
        __syncthreads();
    }

    int buf = 0;
    for (int c = 0; c < nch; c++) {
        int k1 = (c + 1) << 5;
        bool more = (c + 1) < nch;
        if (more) {
            uint32_t bb = (uint32_t)(buf ^ 1) * BUFB;
            CPA16(uBh + bb + cdst0, Bh + (size_t)crow * Kpad + k1 + ckoff);
            CPA16(uBh + bb + cdst1, Bh + (size_t)(crow + 64) * Kpad + k1 + ckoff);
            CPC();
            #pragma unroll
            for (int i = 0; i < 4; i++) {
                if (AIN == 0) {
                    float4 f = *(const float4*)(pf[i] + k1 + akoff);
                    rA[i].x = packh(f.x, f.y);
                    rA[i].y = packh(f.z, f.w);
                } else if (AIN == 1) {
                    rA[i] = *(const uint2*)(p1[i] + k1 + akoff);
                } else {
                    uint2 a = *(const uint2*)(p1[i] + k1 + akoff);
                    uint2 b = *(const uint2*)(p2[i] + k1 + akoff);
                    rA[i].x = mulh2(a.x, b.x);
                    rA[i].y = mulh2(a.y, b.y);
                }
            }
        }
        {
            uint32_t bb = (uint32_t)buf * BUFB;
            #pragma unroll
            for (int ks = 0; ks < 2; ks++) {
                uint32_t bh[8];
                ldmx4(bh[0], bh[1], bh[2], bh[3], uBh + bb + boff0 + ks*32);
                ldmx4(bh[4], bh[5], bh[6], bh[7], uBh + bb + boff1 + ks*32);
                #pragma unroll
                for (int mi = 0; mi < 4; mi++) {
                    uint32_t ah[4];
                    ldmx4(ah[0], ah[1], ah[2], ah[3], uAh + bb + aoff[mi] + ks*32);
                    #pragma unroll
                    for (int ni = 0; ni < 4; ni++)
                        mma16816(acc[mi][ni], ah, &bh[ni*2]);
                }
            }
        }
        if (more) {
            uint32_t bb = (uint32_t)(buf ^ 1) * BUFB;
            #pragma unroll
            for (int i = 0; i < 4; i++) *(uint2*)(ds + bb + asts[i]) = rA[i];
            CPW0();
            __syncthreads();
            buf ^= 1;
        }
    }

    int rowb = blockIdx.x*128 + m0;
    #pragma unroll
    for (int mi = 0; mi < 4; mi++) {
        #pragma unroll
        for (int half = 0; half < 2; half++) {
            int rl = m0 + mi*16 + (lane >> 2) + half*8;
            int row = blockIdx.x*128 + rl;
            if (EPI == 4) {
                float part = 0.f;
                #pragma unroll
                for (int ni = 0; ni < 4; ni++) {
                    int col = n0 + ni*8 + (lane & 3)*2;
                    float v0 = fmaxf(acc[mi][ni][half*2+0] + sbias[col], 0.f);
                    float v1 = fmaxf(acc[mi][ni][half*2+1] + sbias[col+1], 0.f);
                    part = fmaf(v0, sw2[col], part);
                    part = fmaf(v1, sw2[col+1], part);
                }
                part += __shfl_xor_sync(0xffffffffu, part, 1);
                part += __shfl_xor_sync(0xffffffffu, part, 2);
                if ((lane & 3) == 0) atomicAdd(&srow[rl], part);
            } else if (row < M) {
                if (EPI == 3) {
                    int dg = sidx[g_perm[row]];
                    float* Hr = Hout + (size_t)dg * 128;
                    #pragma unroll
                    for (int ni = 0; ni < 4; ni++) {
                        int col = n0 + ni*8 + (lane & 3)*2;
                        float v0 = tanhf(acc[mi][ni][half*2+0] + sbias[col]);
                        float v1 = tanhf(acc[mi][ni][half*2+1] + sbias[col+1]);
                        redv2(Hr + col, v0, v1);
                    }
                } else {
                    size_t cb = (size_t)row * 128;
                    #pragma unroll
                    for (int ni = 0; ni < 4; ni++) {
                        int col = n0 + ni*8 + (lane & 3)*2;
                        float v0 = acc[mi][ni][half*2+0] + sbias[col];
                        float v1 = acc[mi][ni][half*2+1] + sbias[col+1];
                        if (EPI == 1) { v0 = fmaxf(v0, 0.f); v1 = fmaxf(v1, 0.f); }
                        *(uint32_t*)(C + cb + col) = packh(v0, v1);
                    }
                }
            }
        }
    }
    if (EPI == 4) {
        __syncthreads();
        if (tid < 128) {
            int row = blockIdx.x*128 + tid;
            if (row < M) atomicAdd(&Hout[sidx[row]], srow[tid] + br2p[0]);
        }
    }
}

extern "C" void kernel_launch(void* const* d_in, const int* in_sizes, int n_in,
                              void* d_out, int out_size) {
    const int*   Z     = (const int*)  d_in[0];
    const int*   etype = (const int*)  d_in[1];
    const float* dist  = (const float*)d_in[2];
    const int*   src   = (const int*)  d_in[3];
    const int*   dst   = (const int*)  d_in[4];
    const int*   gid   = (const int*)  d_in[5];
    const float* node_emb = (const float*)d_in[6];
    const float* edge_emb = (const float*)d_in[7];
    const float* Wn1 = (const float*)d_in[8];
    const float* bn1 = (const float*)d_in[9];
    const float* Wn2 = (const float*)d_in[10];
    const float* bn2 = (const float*)d_in[11];
    const float* We1 = (const float*)d_in[12];
    const float* be1 = (const float*)d_in[13];
    const float* We2 = (const float*)d_in[14];
    const float* be2 = (const float*)d_in[15];
    const float* Wc  = (const float*)d_in[16];
    const float* bc  = (const float*)d_in[17];
    const float* Wr1 = (const float*)d_in[18];
    const float* br1 = (const float*)d_in[19];
    const float* Wr2 = (const float*)d_in[20];
    const float* br2 = (const float*)d_in[21];

    int N = in_sizes[0], E = in_sizes[1], G = out_size;
    float* out = (float*)d_out;

    static cudaStream_t s1 = 0, s2 = 0;
    static cudaEvent_t evF, evRBF, evA[3], evB[3], evC[3];
    static bool sinit = false;
    if (!sinit) {
        cudaStreamCreateWithFlags(&s1, cudaStreamNonBlocking);
        cudaStreamCreateWithFlags(&s2, cudaStreamNonBlocking);
        cudaEventCreateWithFlags(&evF,   cudaEventDisableTiming);
        cudaEventCreateWithFlags(&evRBF, cudaEventDisableTiming);
        for (int i = 0; i < 3; i++) {
            cudaEventCreateWithFlags(&evA[i], cudaEventDisableTiming);
            cudaEventCreateWithFlags(&evB[i], cudaEventDisableTiming);
            cudaEventCreateWithFlags(&evC[i], cudaEventDisableTiming);
        }
        cudaFuncSetAttribute((const void*)fused_t_ee,    cudaFuncAttributeMaxDynamicSharedMemorySize, DSMEM4);
        cudaFuncSetAttribute((const void*)gemm_mma<1,0>, cudaFuncAttributeMaxDynamicSharedMemorySize, DSMEM2);
        cudaFuncSetAttribute((const void*)gemm_mma<0,1>, cudaFuncAttributeMaxDynamicSharedMemorySize, DSMEM2);
        cudaFuncSetAttribute((const void*)gemm_mma<3,2>, cudaFuncAttributeMaxDynamicSharedMemorySize, DSMEM2);
        cudaFuncSetAttribute((const void*)gemm_mma<4,0>, cudaFuncAttributeMaxDynamicSharedMemorySize, DSMEM2);
        sinit = true;
    }

    void* p;
    float *h, *P;
    __half *ee, *tmp;
    __half *W1h,*We2h,*Wn1h,*Wn2h,*Wch,*Wr1h;
    cudaGetSymbolAddress(&p, g_h);   h   = (float*)p;
    cudaGetSymbolAddress(&p, g_ee);  ee  = (__half*)p;
    cudaGetSymbolAddress(&p, g_tmp); tmp = (__half*)p;
    cudaGetSymbolAddress(&p, g_P);   P   = (float*)p;
    cudaGetSymbolAddress(&p, g_W1h);  W1h  = (__half*)p;
    cudaGetSymbolAddress(&p, g_We2h); We2h = (__half*)p;
    cudaGetSymbolAddress(&p, g_Wn1h); Wn1h = (__half*)p;
    cudaGetSymbolAddress(&p, g_Wn2h); Wn2h = (__half*)p;
    cudaGetSymbolAddress(&p, g_Wch);  Wch  = (__half*)p;
    cudaGetSymbolAddress(&p, g_Wr1h); Wr1h = (__half*)p;

    int gE = (E + 127)/128, gE2 = (E + 63)/64, gN = (N + 127)/128;

    cudaEventRecord(evF, 0);
    cudaStreamWaitEvent(s1, evF, 0);
    cudaStreamWaitEvent(s2, evF, 0);

    // main: out zero + sort + rbf chain
    zero_f_k<<<(G + 255)/256, 256>>>(out, G);
    zero_hist_k<<<(2*NBUCK + 255)/256, 256>>>();
    hist_k<<<148, 512>>>(dist, E);
    scan512_k<<<1, NBUCK>>>();
    scatter_perm_k<<<148, 512>>>(dist, E);
    rbf_klo_k<<<gE2, 64>>>(dist, E);
    rbf_split_k<<<gE2, 64>>>(dist, E);
    cudaEventRecord(evRBF, 0);

    // s1: node-side prep
    init_h_k<<<(N*128 + 255)/256, 256, 0, s1>>>(Z, node_emb, h, N);
    for (int i = 0; i < 3; i++) {
        conv_pad_k<<<(128*128 + 255)/256, 256, 0, s1>>>(Wn1 + (size_t)i*128*128, Wn1h + (size_t)i*128*128, 128, 128, 128, 0, 128, 128*128);
        conv_pad_k<<<(128*128 + 255)/256, 256, 0, s1>>>(Wn2 + (size_t)i*128*128, Wn2h + (size_t)i*128*128, 128, 128, 128, 0, 128, 128*128);
    }
    conv_pad_k<<<(128*128 + 255)/256, 256, 0, s1>>>(Wr1, Wr1h, 128, 128, 128, 0, 128, 128*128);

    // s2: edge-side prep
    for (int i = 0; i < 3; i++) {
        conv_pad_k<<<(512*384 + 255)/256, 256, 0, s2>>>(We1 + (size_t)i*428*428, W1h + (size_t)i*512*384, 428, 300, 428, 128, 384, 512*384);
        conv_pad_k<<<(128*448 + 255)/256, 256, 0, s2>>>(We2 + (size_t)i*128*428, We2h + (size_t)i*128*448, 128, 428, 428, 0, 448, 128*448);
        conv_pad_k<<<(128*128 + 255)/256, 256, 0, s2>>>(Wc  + (size_t)i*128*128, Wch  + (size_t)i*128*128, 128, 128, 128, 0, 128, 128*128);
    }
    p_kernel<<<dim3(400, 3), 448, 0, s2>>>(edge_emb, We1, be1, P);
    cudaStreamWaitEvent(s2, evRBF, 0);

    for (int i = 0; i < 3; i++) {
        __half* eeb = ee + (size_t)(i & 1) * E_MAXE * 128;
        if (i >= 2) cudaStreamWaitEvent(s2, evC[i-2], 0);
        fused_t_ee<<<gE2, 256, DSMEM4, s2>>>(W1h + (size_t)i*512*384,
                                             We2h + (size_t)i*128*448,
                                             P + (size_t)i*400*428, be2 + i*128, etype, eeb, E);
        cudaEventRecord(evB[i], s2);

        if (i >= 1) cudaStreamWaitEvent(s1, evC[i-1], 0);
        gemm_mma<1,0><<<gN, 256, DSMEM2, s1>>>(h, nullptr, nullptr, 128, 128,
            Wn1h + (size_t)i*128*128, 128,
            bn1 + i*128, tmp, N, nullptr, nullptr, nullptr, nullptr, nullptr);
        gemm_mma<0,1><<<gN, 256, DSMEM2, s1>>>(nullptr, tmp, nullptr, 128, 128,
            Wn2h + (size_t)i*128*128, 128,
            bn2 + i*128, tmp, N, nullptr, nullptr, nullptr, nullptr, nullptr);
        cudaEventRecord(evA[i], s1);

        cudaStreamWaitEvent(0, evA[i], 0);
        cudaStreamWaitEvent(0, evB[i], 0);
        gemm_mma<3,2><<<gE, 256, DSMEM2, 0>>>(nullptr, tmp, eeb, 128, 128,
            Wch + (size_t)i*128*128, 128,
            bc + i*128, nullptr, E, src, dst, h, nullptr, nullptr);
        cudaEventRecord(evC[i], 0);
    }

    // fused readout: out[gid[n]] += relu(h@Wr1^T+br1) . Wr2 + br2
    gemm_mma<4,0><<<gN, 256, DSMEM2, 0>>>(h, nullptr, nullptr, 128, 128,
        Wr1h, 128, br1, nullptr, N, nullptr, gid, out, Wr2, br2);
}

// round 17
// speedup vs baseline: 1.0336x; 1.0090x over previous
#include <cuda_runtime.h>
#include <cuda_fp16.h>
#include <math.h>
#include <stdint.h>

#define N_RBF 300
#define NBUCK 512
#define N_MAXN 100352
#define E_MAXE 400384
#define GE2_MAX 6256
#define RBF_STEP (30.0f/299.0f)
#define RBF_INV  (299.0f/30.0f)
#define SLD 40
#define WK 32
#define BUFB 10240
#define DSMEM2 40960
#define DSMEM4 53760

__device__ float  g_h  [(size_t)N_MAXN*128];
__device__ __half g_ee [2*(size_t)E_MAXE*128];
__device__ __half g_tmp[(size_t)N_MAXN*128];
__device__ float  g_P  [3*400*428];
__device__ int    g_perm[E_MAXE];
__device__ int    g_hist[2*NBUCK];
__device__ int    g_klo [GE2_MAX];
__device__ __half g_rAh[(size_t)E_MAXE*WK];
__device__ __half g_W1h[3*512*384];
__device__ __half g_We2h[3*128*448];
__device__ __half g_Wn1h[3*128*128];
__device__ __half g_Wn2h[3*128*128];
__device__ __half g_Wch [3*128*128];
__device__ __half g_Wr1h[128*128];

__device__ __forceinline__ uint32_t smem_u32(const void* p) {
    uint32_t a;
    asm("{ .reg .u64 t; cvta.to.shared.u64 t, %1; cvt.u32.u64 %0, t; }" : "=r"(a) : "l"(p));
    return a;
}
__device__ __forceinline__ void ldmx4(uint32_t& r0, uint32_t& r1, uint32_t& r2, uint32_t& r3, uint32_t a) {
    asm volatile("ldmatrix.sync.aligned.m8n8.x4.shared.b16 {%0,%1,%2,%3}, [%4];"
        : "=r"(r0), "=r"(r1), "=r"(r2), "=r"(r3) : "r"(a));
}
__device__ __forceinline__ void mma16816(float* c, const uint32_t* a, const uint32_t* b) {
    asm volatile("mma.sync.aligned.m16n8k16.row.col.f32.f16.f16.f32 "
        "{%0,%1,%2,%3},{%4,%5,%6,%7},{%8,%9},{%0,%1,%2,%3};"
        : "+f"(c[0]), "+f"(c[1]), "+f"(c[2]), "+f"(c[3])
        : "r"(a[0]), "r"(a[1]), "r"(a[2]), "r"(a[3]), "r"(b[0]), "r"(b[1]));
}
__device__ __forceinline__ uint32_t packh(float a, float b) {
    __half2 t = __floats2half2_rn(a, b);
    return *reinterpret_cast<uint32_t*>(&t);
}
__device__ __forceinline__ uint32_t mulh2(uint32_t a, uint32_t b) {
    __half2 r = __hmul2(*reinterpret_cast<__half2*>(&a), *reinterpret_cast<__half2*>(&b));
    return *reinterpret_cast<uint32_t*>(&r);
}
__device__ __forceinline__ void redv2(float* addr, float v0, float v1) {
    asm volatile("red.global.add.v2.f32 [%0], {%1,%2};" :: "l"(addr), "f"(v0), "f"(v1) : "memory");
}
#define CPA16(dst, src) asm volatile("cp.async.cg.shared.global [%0], [%1], 16;" :: "r"(dst), "l"(src))
#define CPC()  asm volatile("cp.async.commit_group;" ::: "memory")
#define CPW0() asm volatile("cp.async.wait_group 0;" ::: "memory")

__global__ void zero_hist_k() { int i = blockIdx.x*256 + threadIdx.x; if (i < 2*NBUCK) g_hist[i] = 0; }
__global__ void zero_f_k(float* p, int n) { int i = blockIdx.x*256 + threadIdx.x; if (i < n) p[i] = 0.f; }
__device__ __forceinline__ int bucket_of(float d) {
    int b = (int)(d * (512.0f/30.0f));
    return min(max(b, 0), NBUCK-1);
}
__global__ void hist_k(const float* __restrict__ dist, int E) {
    __shared__ int lh[NBUCK];
    int tid = threadIdx.x;
    int per = (E + gridDim.x - 1) / gridDim.x;
    int lo = blockIdx.x * per, hi = min(E, lo + per);
    for (int i = tid; i < NBUCK; i += 512) lh[i] = 0;
    __syncthreads();
    for (int e = lo + tid; e < hi; e += 512) atomicAdd(&lh[bucket_of(dist[e])], 1);
    __syncthreads();
    for (int i = tid; i < NBUCK; i += 512) if (lh[i]) atomicAdd(&g_hist[i], lh[i]);
}
__global__ void scan512_k() {
    __shared__ int s[NBUCK];
    int tid = threadIdx.x;
    int v0 = g_hist[tid];
    s[tid] = v0; __syncthreads();
    for (int off = 1; off < NBUCK; off <<= 1) {
        int v = 0;
        if (tid >= off) v = s[tid - off];
        __syncthreads(); s[tid] += v; __syncthreads();
    }
    g_hist[NBUCK + tid] = s[tid] - v0;
}
__global__ void scatter_perm_k(const float* __restrict__ dist, int E) {
    __shared__ int lh[NBUCK], base[NBUCK];
    int tid = threadIdx.x;
    int per = (E + gridDim.x - 1) / gridDim.x;
    int lo = blockIdx.x * per, hi = min(E, lo + per);
    for (int i = tid; i < NBUCK; i += 512) lh[i] = 0;
    __syncthreads();
    for (int e = lo + tid; e < hi; e += 512) atomicAdd(&lh[bucket_of(dist[e])], 1);
    __syncthreads();
    for (int i = tid; i < NBUCK; i += 512)
        base[i] = lh[i] ? atomicAdd(&g_hist[NBUCK + i], lh[i]) : 0;
    __syncthreads();
    for (int i = tid; i < NBUCK; i += 512) lh[i] = 0;
    __syncthreads();
    for (int e = lo + tid; e < hi; e += 512) {
        int b = bucket_of(dist[e]);
        int r = atomicAdd(&lh[b], 1);
        g_perm[base[b] + r] = e;
    }
}
__global__ void init_h_k(const int* __restrict__ Z, const float* __restrict__ ne,
                         float* __restrict__ h, int N) {
    int idx = blockIdx.x*256 + threadIdx.x;
    if (idx < N*128) h[idx] = ne[Z[idx >> 7]*128 + (idx & 127)];
}
__global__ void conv_pad_k(const float* __restrict__ src, __half* __restrict__ dh,
                           int R, int Ks, int ld, int off, int Kpad, int tot) {
    int idx = blockIdx.x*256 + threadIdx.x;
    if (idx < tot) {
        int r = idx / Kpad, k = idx % Kpad;
        float v = (r < R && k < Ks) ? src[(size_t)r*ld + off + k] : 0.f;
        dh[idx] = __float2half_rn(v);
    }
}
__global__ void p_kernel(const float* __restrict__ edge_emb, const float* __restrict__ We1,
                         const float* __restrict__ be1, float* __restrict__ P) {
    int ty = blockIdx.x, layer = blockIdx.y, j = threadIdx.x;
    __shared__ float em[128];
    if (j < 128) em[j] = edge_emb[ty*128 + j];
    __syncthreads();
    if (j < 428) {
        const float* wrow = We1 + ((size_t)layer*428 + j)*428;
        float acc = be1[layer*428 + j];
        #pragma unroll 8
        for (int k = 0; k < 128; k++) acc = fmaf(em[k], wrow[k], acc);
        P[((size_t)layer*400 + ty)*428 + j] = acc;
    }
}
__global__ void rbf_klo_k(const float* __restrict__ dist, int E) {
    __shared__ float s[64];
    int tid = threadIdx.x, gr = blockIdx.x*64 + tid;
    s[tid] = dist[g_perm[min(gr, E-1)]];
    __syncthreads();
    for (int o = 32; o > 0; o >>= 1) {
        if (tid < o) s[tid] = fminf(s[tid], s[tid + o]);
        __syncthreads();
    }
    if (tid == 0) {
        int k = (int)floorf((s[0] - 1.055f) * RBF_INV);
        if (k < 0) k = 0;
        g_klo[blockIdx.x] = k & ~7;
    }
}
__global__ void rbf_split_k(const float* __restrict__ dist, int E) {
    int tid = threadIdx.x, gr = blockIdx.x*64 + tid;
    float d = dist[g_perm[min(gr, E-1)]];
    int k0 = g_klo[blockIdx.x];
    float vals[WK];
    #pragma unroll
    for (int i = 0; i < WK; i++) vals[i] = 0.f;
    int icen = (int)(d * RBF_INV) - k0;
    int ilo = max(0, icen - 10);
    int ihi = min(min(WK-1, icen + 10), 299 - k0);
    for (int i = ilo; i <= ihi; i++) {
        float x = d - (float)(k0 + i) * RBF_STEP;
        vals[i] = __expf(-RBF_INV * x * x);
    }
    size_t base = (size_t)gr * WK;
    #pragma unroll
    for (int i = 0; i < WK; i += 8) {
        uint4 H;
        H.x = packh(vals[i+0], vals[i+1]);
        H.y = packh(vals[i+2], vals[i+3]);
        H.z = packh(vals[i+4], vals[i+5]);
        H.w = packh(vals[i+6], vals[i+7]);
        *(uint4*)(g_rAh + base + i) = H;
    }
}

// ============ fused t -> ee kernel, single-barrier-per-chunk pipeline ============
// smem: T 2x5120 (0..10240), A 10240..15360, W1 3x2560 (15360..23040), W2 3x10240 (23040..53760)
__global__ void __launch_bounds__(256, 2)
fused_t_ee(const __half* __restrict__ W1, const __half* __restrict__ W2,
           const float* __restrict__ P, const float* __restrict__ be2,
           const int* __restrict__ etype, __half* __restrict__ ee, int E) {
    extern __shared__ char ds[];
    __shared__ int sety[64];
    __shared__ float sbias[128];
    int tid = threadIdx.x, lane = tid & 31, warp = tid >> 5, bx = blockIdx.x;
    int klo = g_klo[bx];
    if (tid < 64) sety[tid] = etype[g_perm[min(bx*64 + tid, E-1)]];
    if (tid < 128) sbias[tid] = be2[tid];
    uint32_t b0 = smem_u32(ds);
    uint32_t uT  = b0;
    uint32_t uAh = b0 + 10240;
    uint32_t uW1 = b0 + 15360;
    uint32_t uW2 = b0 + 23040;

    // prologue: A tile + chunk 0 weights -> slot 0
    {
        int row = tid >> 2, kk = (tid & 3) << 3;
        CPA16(uAh + (uint32_t)(row*SLD + kk)*2, g_rAh + (size_t)(bx*64 + row)*WK + kk);
    }
    if (tid < 128) {
        int row = tid >> 2, kk = (tid & 3) << 3;
        CPA16(uW1 + (uint32_t)(row*SLD + kk)*2, W1 + (size_t)row*384 + klo + kk);
    }
    for (int i = tid; i < 512; i += 256) {
        int row = i >> 2, kk = (i & 3) * 8;
        CPA16(uW2 + (uint32_t)(row*SLD + kk)*2, W2 + (size_t)row*448 + kk);
    }
    CPC(); CPW0();
    __syncthreads();

    int arow = lane & 15, acol = (lane >> 4) << 3;
    int brow = (lane & 7) + ((lane >> 1) & 8), bcol = lane & 8;
    int r1 = (warp >> 1)*16, c1 = (warp & 1)*16;
    uint32_t a1off = (uint32_t)((r1 + arow)*SLD + acol)*2;
    uint32_t b1off = (uint32_t)((c1 + brow)*SLD + bcol)*2;
    int m0 = (warp >> 2)*32, n0 = (warp & 3)*32;
    uint32_t a2off[2];
    #pragma unroll
    for (int mi = 0; mi < 2; mi++) a2off[mi] = (uint32_t)((m0 + mi*16 + arow)*SLD + acol)*2;
    uint32_t b2off0 = (uint32_t)((n0 + brow)*SLD + bcol)*2;
    uint32_t b2off1 = (uint32_t)((n0 + 16 + brow)*SLD + bcol)*2;
    int lrow = lane >> 2, lcol = (lane & 3)*2;

    float eacc[2][4][4];
    #pragma unroll
    for (int mi = 0; mi < 2; mi++)
        #pragma unroll
        for (int ni = 0; ni < 4; ni++)
            #pragma unroll
            for (int q = 0; q < 4; q++) eacc[mi][ni][q] = 0.f;

    int ws = 0;       // W slot of current chunk (mod 3)
    int tb = 0;       // T buffer of current chunk (mod 2)
    for (int c = 0; c < 14; c++) {
        // prefetch chunk c+1 into W slot (ws+1)%3 — safe: MMA2(c-1) used slot (ws+2)%3
        if (c < 13) {
            uint32_t nw = (uint32_t)((ws + 1) % 3);
            if (tid < 128) {
                int row = tid >> 2, kk = (tid & 3) << 3;
                CPA16(uW1 + nw*2560 + (uint32_t)(row*SLD + kk)*2,
                      W1 + (size_t)((c+1)*32 + row)*384 + klo + kk);
            }
            for (int i = tid; i < 512; i += 256) {
                int row = i >> 2, kk = (i & 3) * 8;
                CPA16(uW2 + nw*10240 + (uint32_t)(row*SLD + kk)*2,
                      W2 + (size_t)row*448 + (c+1)*32 + kk);
            }
            CPC();
        }
        // MMA1: t_chunk[64,32], K=32
        float acc1[2][4];
        #pragma unroll
        for (int ni = 0; ni < 2; ni++)
            #pragma unroll
            for (int q = 0; q < 4; q++) acc1[ni][q] = 0.f;
        {
            uint32_t w1b = (uint32_t)ws * 2560;
            #pragma unroll
            for (int ks = 0; ks < 2; ks++) {
                uint32_t ah[4], bh[4];
                ldmx4(ah[0], ah[1], ah[2], ah[3], uAh + a1off + ks*32);
                ldmx4(bh[0], bh[1], bh[2], bh[3], uW1 + w1b + b1off + ks*32);
                #pragma unroll
                for (int ni = 0; ni < 2; ni++)
                    mma16816(acc1[ni], ah, &bh[ni*2]);
            }
        }
        // epilogue1: +P, relu, pack fp16 -> T[tb]
        {
            int gcb = c*32;
            uint32_t tbb = (uint32_t)tb * 5120;
            #pragma unroll
            for (int half = 0; half < 2; half++) {
                int r = r1 + lrow + half*8;
                const float* Pr = P + (size_t)sety[r]*428;
                #pragma unroll
                for (int ni = 0; ni < 2; ni++) {
                    int col = c1 + ni*8 + lcol;
                    int gcol = gcb + col;
                    float v0 = 0.f, v1 = 0.f;
                    if (gcol < 428) {
                        float2 pv = *(const float2*)(Pr + gcol);
                        v0 = fmaxf(acc1[ni][half*2+0] + pv.x, 0.f);
                        v1 = fmaxf(acc1[ni][half*2+1] + pv.y, 0.f);
                    }
                    *(uint32_t*)(ds + tbb + (uint32_t)(r*SLD + col)*2) = packh(v0, v1);
                }
            }
        }
        CPW0();
        __syncthreads();
        // MMA2: ee += t_chunk @ We2_chunk^T  (reads T[tb], W2[ws])
        {
            uint32_t w2b = (uint32_t)ws * 10240;
            uint32_t tbb = (uint32_t)tb * 5120;
            #pragma unroll
            for (int ks = 0; ks < 2; ks++) {
                uint32_t bh[8];
                ldmx4(bh[0], bh[1], bh[2], bh[3], uW2 + w2b + b2off0 + ks*32);
                ldmx4(bh[4], bh[5], bh[6], bh[7], uW2 + w2b + b2off1 + ks*32);
                #pragma unroll
                for (int mi = 0; mi < 2; mi++) {
                    uint32_t ah[4];
                    ldmx4(ah[0], ah[1], ah[2], ah[3], uT + tbb + a2off[mi] + ks*32);
                    #pragma unroll
                    for (int ni = 0; ni < 4; ni++)
                        mma16816(eacc[mi][ni], ah, &bh[ni*2]);
                }
            }
        }
        ws = (ws + 1) % 3;
        tb ^= 1;
    }

    int rowb = bx*64 + m0;
    #pragma unroll
    for (int mi = 0; mi < 2; mi++) {
        #pragma unroll
        for (int half = 0; half < 2; half++) {
            int row = rowb + mi*16 + lrow + half*8;
            if (row < E) {
                size_t cb = (size_t)row * 128;
                #pragma unroll
                for (int ni = 0; ni < 4; ni++) {
                    int col = n0 + ni*8 + lcol;
                    *(uint32_t*)(ee + cb + col) =
                        packh(eacc[mi][ni][half*2+0] + sbias[col],
                              eacc[mi][ni][half*2+1] + sbias[col+1]);
                }
            }
        }
    }
}

// ============ generic pipelined GEMM (single fp16) ============
// EPI: 0 store fp16, 1 relu store fp16, 3 tanh + red.v2 scatter,
//      4 readout: dot(relu(acc+bias), W2r) + br2 -> atomicAdd out[sidx[row]]
// AIN: 0 fp32 rows (Af); 1 fp16 rows (A1); 2 product A1[gidx[perm[row]]]*A2[row]
template<int EPI, int AIN>
__global__ void __launch_bounds__(256)
gemm_mma(const float* __restrict__ Af, const __half* __restrict__ A1,
         const __half* __restrict__ A2, int lda, int Kloop,
         const __half* __restrict__ Bh, int Kpad,
         const float* __restrict__ bias, __half* __restrict__ C, int M,
         const int* __restrict__ gidx, const int* __restrict__ sidx, float* __restrict__ Hout,
         const float* __restrict__ W2r, const float* __restrict__ br2p) {
    extern __shared__ char ds[];
    __shared__ float sbias[128];
    __shared__ float sw2[128];
    __shared__ float srow[128];
    int tid = threadIdx.x, lane = tid & 31, warp = tid >> 5;
    if (tid < 128) {
        sbias[tid] = bias[tid];
        if (EPI == 4) { sw2[tid] = W2r[tid]; srow[tid] = 0.f; }
    }

    uint32_t b0 = smem_u32(ds);
    uint32_t uAh = b0, uBh = b0 + 2*BUFB;

    const float* pf[4];
    const __half *p1[4], *p2[4];
    #pragma unroll
    for (int i = 0; i < 4; i++) {
        int r = blockIdx.x*128 + i*32 + (tid >> 3);
        int rc = min(r, M-1);
        if (AIN == 0) pf[i] = Af + (size_t)rc * lda;
        else if (AIN == 1) p1[i] = A1 + (size_t)rc * lda;
        else {
            p1[i] = A1 + (size_t)gidx[g_perm[rc]] * 128;
            p2[i] = A2 + (size_t)rc * 128;
        }
    }
    int akoff = (tid & 7) << 2;
    int ckoff = (tid & 3) << 3;
    int crow  = tid >> 2;
    uint32_t cdst0 = ((uint32_t)crow * SLD + ckoff) * 2;
    uint32_t cdst1 = ((uint32_t)(crow + 64) * SLD + ckoff) * 2;
    uint32_t asts[4];
    #pragma unroll
    for (int i = 0; i < 4; i++) asts[i] = ((uint32_t)(i*32 + (tid >> 3)) * SLD + akoff) * 2;

    int m0 = (warp >> 2) * 64, n0 = (warp & 3) * 32;
    int arow = lane & 15, acol = (lane >> 4) << 3;
    int brow = (lane & 7) + ((lane >> 1) & 8), bcol = lane & 8;
    uint32_t aoff[4];
    #pragma unroll
    for (int mi = 0; mi < 4; mi++) aoff[mi] = ((m0 + mi*16 + arow)*SLD + acol) * 2;
    uint32_t boff0 = ((n0 + brow)*SLD + bcol) * 2;
    uint32_t boff1 = ((n0 + 16 + brow)*SLD + bcol) * 2;

    float acc[4][4][4];
    #pragma unroll
    for (int mi = 0; mi < 4; mi++)
        #pragma unroll
        for (int ni = 0; ni < 4; ni++)
            #pragma unroll
            for (int q = 0; q < 4; q++) acc[mi][ni][q] = 0.f;

    uint2 rA[4];
    int nch = Kloop >> 5;

    {
        CPA16(uBh + cdst0, Bh + (size_t)crow * Kpad + ckoff);
        CPA16(uBh + cdst1, Bh + (size_t)(crow + 64) * Kpad + ckoff);
        CPC();
        #pragma unroll
        for (int i = 0; i < 4; i++) {
            if (AIN == 0) {
                float4 f = *(const float4*)(pf[i] + akoff);
                rA[i].x = packh(f.x, f.y);
                rA[i].y = packh(f.z, f.w);
            } else if (AIN == 1) {
                rA[i] = *(const uint2*)(p1[i] + akoff);
            } else {
                uint2 a = *(const uint2*)(p1[i] + akoff);
                uint2 b = *(const uint2*)(p2[i] + akoff);
                rA[i].x = mulh2(a.x, b.x);
                rA[i].y = mulh2(a.y, b.y);
            }
        }
        #pragma unroll
        for (int i = 0; i < 4; i++) *(uint2*)(ds + asts[i]) = rA[i];
        CPW0();
        __syncthreads();
    }

    int buf = 0;
    for (int c = 0; c < nch; c++) {
        int k1 = (c + 1) << 5;
        bool more = (c + 1) < nch;
        if (more) {
            uint32_t bb = (uint32_t)(buf ^ 1) * BUFB;
            CPA16(uBh + bb + cdst0, Bh + (size_t)crow * Kpad + k1 + ckoff);
            CPA16(uBh + bb + cdst1, Bh + (size_t)(crow + 64) * Kpad + k1 + ckoff);
            CPC();
            #pragma unroll
            for (int i = 0; i < 4; i++) {
                if (AIN == 0) {
                    float4 f = *(const float4*)(pf[i] + k1 + akoff);
                    rA[i].x = packh(f.x, f.y);
                    rA[i].y = packh(f.z, f.w);
                } else if (AIN == 1) {
                    rA[i] = *(const uint2*)(p1[i] + k1 + akoff);
                } else {
                    uint2 a = *(const uint2*)(p1[i] + k1 + akoff);
                    uint2 b = *(const uint2*)(p2[i] + k1 + akoff);
                    rA[i].x = mulh2(a.x, b.x);
                    rA[i].y = mulh2(a.y, b.y);
                }
            }
        }
        {
            uint32_t bb = (uint32_t)buf * BUFB;
            #pragma unroll
            for (int ks = 0; ks < 2; ks++) {
                uint32_t bh[8];
                ldmx4(bh[0], bh[1], bh[2], bh[3], uBh + bb + boff0 + ks*32);
                ldmx4(bh[4], bh[5], bh[6], bh[7], uBh + bb + boff1 + ks*32);
                #pragma unroll
                for (int mi = 0; mi < 4; mi++) {
                    uint32_t ah[4];
                    ldmx4(ah[0], ah[1], ah[2], ah[3], uAh + bb + aoff[mi] + ks*32);
                    #pragma unroll
                    for (int ni = 0; ni < 4; ni++)
                        mma16816(acc[mi][ni], ah, &bh[ni*2]);
                }
            }
        }
        if (more) {
            uint32_t bb = (uint32_t)(buf ^ 1) * BUFB;
            #pragma unroll
            for (int i = 0; i < 4; i++) *(uint2*)(ds + bb + asts[i]) = rA[i];
            CPW0();
            __syncthreads();
            buf ^= 1;
        }
    }

    int rowb = blockIdx.x*128 + m0;
    #pragma unroll
    for (int mi = 0; mi < 4; mi++) {
        #pragma unroll
        for (int half = 0; half < 2; half++) {
            int rl = m0 + mi*16 + (lane >> 2) + half*8;
            int row = blockIdx.x*128 + rl;
            if (EPI == 4) {
                float part = 0.f;
                #pragma unroll
                for (int ni = 0; ni < 4; ni++) {
                    int col = n0 + ni*8 + (lane & 3)*2;
                    float v0 = fmaxf(acc[mi][ni][half*2+0] + sbias[col], 0.f);
                    float v1 = fmaxf(acc[mi][ni][half*2+1] + sbias[col+1], 0.f);
                    part = fmaf(v0, sw2[col], part);
                    part = fmaf(v1, sw2[col+1], part);
                }
                part += __shfl_xor_sync(0xffffffffu, part, 1);
                part += __shfl_xor_sync(0xffffffffu, part, 2);
                if ((lane & 3) == 0) atomicAdd(&srow[rl], part);
            } else if (row < M) {
                if (EPI == 3) {
                    int dg = sidx[g_perm[row]];
                    float* Hr = Hout + (size_t)dg * 128;
                    #pragma unroll
                    for (int ni = 0; ni < 4; ni++) {
                        int col = n0 + ni*8 + (lane & 3)*2;
                        float v0 = tanhf(acc[mi][ni][half*2+0] + sbias[col]);
                        float v1 = tanhf(acc[mi][ni][half*2+1] + sbias[col+1]);
                        redv2(Hr + col, v0, v1);
                    }
                } else {
                    size_t cb = (size_t)row * 128;
                    #pragma unroll
                    for (int ni = 0; ni < 4; ni++) {
                        int col = n0 + ni*8 + (lane & 3)*2;
                        float v0 = acc[mi][ni][half*2+0] + sbias[col];
                        float v1 = acc[mi][ni][half*2+1] + sbias[col+1];
                        if (EPI == 1) { v0 = fmaxf(v0, 0.f); v1 = fmaxf(v1, 0.f); }
                        *(uint32_t*)(C + cb + col) = packh(v0, v1);
                    }
                }
            }
        }
    }
    if (EPI == 4) {
        __syncthreads();
        if (tid < 128) {
            int row = blockIdx.x*128 + tid;
            if (row < M) atomicAdd(&Hout[sidx[row]], srow[tid] + br2p[0]);
        }
    }
}

extern "C" void kernel_launch(void* const* d_in, const int* in_sizes, int n_in,
                              void* d_out, int out_size) {
    const int*   Z     = (const int*)  d_in[0];
    const int*   etype = (const int*)  d_in[1];
    const float* dist  = (const float*)d_in[2];
    const int*   src   = (const int*)  d_in[3];
    const int*   dst   = (const int*)  d_in[4];
    const int*   gid   = (const int*)  d_in[5];
    const float* node_emb = (const float*)d_in[6];
    const float* edge_emb = (const float*)d_in[7];
    const float* Wn1 = (const float*)d_in[8];
    const float* bn1 = (const float*)d_in[9];
    const float* Wn2 = (const float*)d_in[10];
    const float* bn2 = (const float*)d_in[11];
    const float* We1 = (const float*)d_in[12];
    const float* be1 = (const float*)d_in[13];
    const float* We2 = (const float*)d_in[14];
    const float* be2 = (const float*)d_in[15];
    const float* Wc  = (const float*)d_in[16];
    const float* bc  = (const float*)d_in[17];
    const float* Wr1 = (const float*)d_in[18];
    const float* br1 = (const float*)d_in[19];
    const float* Wr2 = (const float*)d_in[20];
    const float* br2 = (const float*)d_in[21];

    int N = in_sizes[0], E = in_sizes[1], G = out_size;
    float* out = (float*)d_out;

    static cudaStream_t s1 = 0, s2 = 0;
    static cudaEvent_t evF, evRBF, evA[3], evB[3], evC[3];
    static bool sinit = false;
    if (!sinit) {
        cudaStreamCreateWithFlags(&s1, cudaStreamNonBlocking);
        cudaStreamCreateWithFlags(&s2, cudaStreamNonBlocking);
        cudaEventCreateWithFlags(&evF,   cudaEventDisableTiming);
        cudaEventCreateWithFlags(&evRBF, cudaEventDisableTiming);
        for (int i = 0; i < 3; i++) {
            cudaEventCreateWithFlags(&evA[i], cudaEventDisableTiming);
            cudaEventCreateWithFlags(&evB[i], cudaEventDisableTiming);
            cudaEventCreateWithFlags(&evC[i], cudaEventDisableTiming);
        }
        cudaFuncSetAttribute((const void*)fused_t_ee,    cudaFuncAttributeMaxDynamicSharedMemorySize, DSMEM4);
        cudaFuncSetAttribute((const void*)gemm_mma<1,0>, cudaFuncAttributeMaxDynamicSharedMemorySize, DSMEM2);
        cudaFuncSetAttribute((const void*)gemm_mma<0,1>, cudaFuncAttributeMaxDynamicSharedMemorySize, DSMEM2);
        cudaFuncSetAttribute((const void*)gemm_mma<3,2>, cudaFuncAttributeMaxDynamicSharedMemorySize, DSMEM2);
        cudaFuncSetAttribute((const void*)gemm_mma<4,0>, cudaFuncAttributeMaxDynamicSharedMemorySize, DSMEM2);
        sinit = true;
    }

    void* p;
    float *h, *P;
    __half *ee, *tmp;
    __half *W1h,*We2h,*Wn1h,*Wn2h,*Wch,*Wr1h;
    cudaGetSymbolAddress(&p, g_h);   h   = (float*)p;
    cudaGetSymbolAddress(&p, g_ee);  ee  = (__half*)p;
    cudaGetSymbolAddress(&p, g_tmp); tmp = (__half*)p;
    cudaGetSymbolAddress(&p, g_P);   P   = (float*)p;
    cudaGetSymbolAddress(&p, g_W1h);  W1h  = (__half*)p;
    cudaGetSymbolAddress(&p, g_We2h); We2h = (__half*)p;
    cudaGetSymbolAddress(&p, g_Wn1h); Wn1h = (__half*)p;
    cudaGetSymbolAddress(&p, g_Wn2h); Wn2h = (__half*)p;
    cudaGetSymbolAddress(&p, g_Wch);  Wch  = (__half*)p;
    cudaGetSymbolAddress(&p, g_Wr1h); Wr1h = (__half*)p;

    int gE = (E + 127)/128, gE2 = (E + 63)/64, gN = (N + 127)/128;

    cudaEventRecord(evF, 0);
    cudaStreamWaitEvent(s1, evF, 0);
    cudaStreamWaitEvent(s2, evF, 0);

    // main: out zero + sort + rbf chain
    zero_f_k<<<(G + 255)/256, 256>>>(out, G);
    zero_hist_k<<<(2*NBUCK + 255)/256, 256>>>();
    hist_k<<<148, 512>>>(dist, E);
    scan512_k<<<1, NBUCK>>>();
    scatter_perm_k<<<148, 512>>>(dist, E);
    rbf_klo_k<<<gE2, 64>>>(dist, E);
    rbf_split_k<<<gE2, 64>>>(dist, E);
    cudaEventRecord(evRBF, 0);

    // s1: node-side prep
    init_h_k<<<(N*128 + 255)/256, 256, 0, s1>>>(Z, node_emb, h, N);
    for (int i = 0; i < 3; i++) {
        conv_pad_k<<<(128*128 + 255)/256, 256, 0, s1>>>(Wn1 + (size_t)i*128*128, Wn1h + (size_t)i*128*128, 128, 128, 128, 0, 128, 128*128);
        conv_pad_k<<<(128*128 + 255)/256, 256, 0, s1>>>(Wn2 + (size_t)i*128*128, Wn2h + (size_t)i*128*128, 128, 128, 128, 0, 128, 128*128);
    }
    conv_pad_k<<<(128*128 + 255)/256, 256, 0, s1>>>(Wr1, Wr1h, 128, 128, 128, 0, 128, 128*128);

    // s2: edge-side prep
    for (int i = 0; i < 3; i++) {
        conv_pad_k<<<(512*384 + 255)/256, 256, 0, s2>>>(We1 + (size_t)i*428*428, W1h + (size_t)i*512*384, 428, 300, 428, 128, 384, 512*384);
        conv_pad_k<<<(128*448 + 255)/256, 256, 0, s2>>>(We2 + (size_t)i*128*428, We2h + (size_t)i*128*448, 128, 428, 428, 0, 448, 128*448);
        conv_pad_k<<<(128*128 + 255)/256, 256, 0, s2>>>(Wc  + (size_t)i*128*128, Wch  + (size_t)i*128*128, 128, 128, 128, 0, 128, 128*128);
    }
    p_kernel<<<dim3(400, 3), 448, 0, s2>>>(edge_emb, We1, be1, P);
    cudaStreamWaitEvent(s2, evRBF, 0);

    for (int i = 0; i < 3; i++) {
        __half* eeb = ee + (size_t)(i & 1) * E_MAXE * 128;
        if (i >= 2) cudaStreamWaitEvent(s2, evC[i-2], 0);
        fused_t_ee<<<gE2, 256, DSMEM4, s2>>>(W1h + (size_t)i*512*384,
                                             We2h + (size_t)i*128*448,
                                             P + (size_t)i*400*428, be2 + i*128, etype, eeb, E);
        cudaEventRecord(evB[i], s2);

        if (i >= 1) cudaStreamWaitEvent(s1, evC[i-1], 0);
        gemm_mma<1,0><<<gN, 256, DSMEM2, s1>>>(h, nullptr, nullptr, 128, 128,
            Wn1h + (size_t)i*128*128, 128,
            bn1 + i*128, tmp, N, nullptr, nullptr, nullptr, nullptr, nullptr);
        gemm_mma<0,1><<<gN, 256, DSMEM2, s1>>>(nullptr, tmp, nullptr, 128, 128,
            Wn2h + (size_t)i*128*128, 128,
            bn2 + i*128, tmp, N, nullptr, nullptr, nullptr, nullptr, nullptr);
        cudaEventRecord(evA[i], s1);

        cudaStreamWaitEvent(0, evA[i], 0);
        cudaStreamWaitEvent(0, evB[i], 0);
        gemm_mma<3,2><<<gE, 256, DSMEM2, 0>>>(nullptr, tmp, eeb, 128, 128,
            Wch + (size_t)i*128*128, 128,
            bc + i*128, nullptr, E, src, dst, h, nullptr, nullptr);
        cudaEventRecord(evC[i], 0);
    }

    // fused readout: out[gid[n]] += relu(h@Wr1^T+br1) . Wr2 + br2
    gemm_mma<4,0><<<gN, 256, DSMEM2, 0>>>(h, nullptr, nullptr, 128, 128,
        Wr1h, 128, br1, nullptr, N, nullptr, gid, out, Wr2, br2);
}